// round 13
// baseline (speedup 1.0000x reference)
#include <cuda_runtime.h>
#include <cuda_bf16.h>
#include <math.h>
#include <cstdint>

// ---------------- problem constants ----------------
#define SQ     2048
#define HID    2048
#define VOC    32000
#define NHEAD  16
#define NKVH   4
#define HDIM   128
#define FFD    8192
#define NLAYER 4
#define NQKV   3072   // 2048 + 512 + 512
#define NFF2   16384  // fused gate|up (interleaved by 8-col groups)

#define SH  (SQ * HID)
#define SFF (SQ * FFD)

__device__ float g_scratch[(size_t)SH + (size_t)SQ * NQKV];
__device__ __nv_bfloat16 g_ahi[(size_t)SFF];
__device__ __nv_bfloat16 g_alo[(size_t)SFF];
__device__ __nv_bfloat16 g_fhi[(size_t)SFF];
__device__ __nv_bfloat16 g_flo[(size_t)SFF];
__device__ __nv_bfloat16 g_whi[(size_t)HID * VOC];
__device__ __nv_bfloat16 g_wlo[(size_t)HID * VOC];
__device__ __nv_bfloat16 g_qkvhi[(size_t)SQ * NQKV];
__device__ __nv_bfloat16 g_qkvlo[(size_t)SQ * NQKV];

// ======================= helpers =======================
__device__ __forceinline__ uint32_t smem_u32(const void* p) {
    uint32_t a;
    asm("{ .reg .u64 t; cvta.to.shared.u64 t, %1; cvt.u32.u64 %0, t; }"
        : "=r"(a) : "l"(p));
    return a;
}
__device__ __forceinline__ void ldsm_x4(uint32_t* r, uint32_t addr) {
    asm volatile("ldmatrix.sync.aligned.m8n8.x4.shared.b16 {%0,%1,%2,%3}, [%4];"
                 : "=r"(r[0]), "=r"(r[1]), "=r"(r[2]), "=r"(r[3]) : "r"(addr));
}
__device__ __forceinline__ void ldsm_x2(uint32_t* r, uint32_t addr) {
    asm volatile("ldmatrix.sync.aligned.m8n8.x2.shared.b16 {%0,%1}, [%2];"
                 : "=r"(r[0]), "=r"(r[1]) : "r"(addr));
}
__device__ __forceinline__ void ldsm_x4t(uint32_t* r, uint32_t addr) {
    asm volatile("ldmatrix.sync.aligned.m8n8.x4.trans.shared.b16 {%0,%1,%2,%3}, [%4];"
                 : "=r"(r[0]), "=r"(r[1]), "=r"(r[2]), "=r"(r[3]) : "r"(addr));
}
__device__ __forceinline__ void mma_bf16(float* c, const uint32_t* a,
                                         const uint32_t* b) {
    asm volatile("mma.sync.aligned.m16n8k16.row.col.f32.bf16.bf16.f32 "
                 "{%0,%1,%2,%3}, {%4,%5,%6,%7}, {%8,%9}, {%0,%1,%2,%3};"
                 : "+f"(c[0]), "+f"(c[1]), "+f"(c[2]), "+f"(c[3])
                 : "r"(a[0]), "r"(a[1]), "r"(a[2]), "r"(a[3]),
                   "r"(b[0]), "r"(b[1]));
}
__device__ __forceinline__ uint32_t pack2(__nv_bfloat16 a, __nv_bfloat16 b) {
    uint16_t ua = *(uint16_t*)&a, ub = *(uint16_t*)&b;
    return ((uint32_t)ub << 16) | (uint32_t)ua;
}
__device__ __forceinline__ void split4(float4 f, uint2& hi, uint2& lo) {
    __nv_bfloat16 hx = __float2bfloat16_rn(f.x);
    __nv_bfloat16 hy = __float2bfloat16_rn(f.y);
    __nv_bfloat16 hz = __float2bfloat16_rn(f.z);
    __nv_bfloat16 hw = __float2bfloat16_rn(f.w);
    __nv_bfloat16 lx = __float2bfloat16_rn(f.x - __bfloat162float(hx));
    __nv_bfloat16 ly = __float2bfloat16_rn(f.y - __bfloat162float(hy));
    __nv_bfloat16 lz = __float2bfloat16_rn(f.z - __bfloat162float(hz));
    __nv_bfloat16 lw = __float2bfloat16_rn(f.w - __bfloat162float(hw));
    hi = make_uint2(pack2(hx, hy), pack2(hz, hw));
    lo = make_uint2(pack2(lx, ly), pack2(lz, lw));
}
__device__ __forceinline__ void split1(float x, uint16_t& h, uint16_t& l) {
    __nv_bfloat16 hb = __float2bfloat16_rn(x);
    __nv_bfloat16 lb = __float2bfloat16_rn(x - __bfloat162float(hb));
    h = *(uint16_t*)&hb;
    l = *(uint16_t*)&lb;
}
__device__ __forceinline__ uint32_t splitpack(float a, float b, uint32_t& lo) {
    uint16_t ha, la, hb, lb;
    split1(a, ha, la);
    split1(b, hb, lb);
    lo = ((uint32_t)lb << 16) | la;
    return ((uint32_t)hb << 16) | ha;
}
__device__ __forceinline__ float silu(float x) {
    return x / (1.f + expf(-x));
}
#define CP16(dst, src) \
    asm volatile("cp.async.cg.shared.global [%0], [%1], 16;" :: "r"(dst), "l"(src))
#define CP_COMMIT() asm volatile("cp.async.commit_group;" ::: "memory")

// ---------------- weight splits ----------------
__global__ void split_kernel(const float* __restrict__ src,
                             __nv_bfloat16* __restrict__ hi,
                             __nv_bfloat16* __restrict__ lo, int nT) {
    int i = blockIdx.x * blockDim.x + threadIdx.x;
    float4 f[4];
#pragma unroll
    for (int j = 0; j < 4; j++) f[j] = ((const float4*)src)[4 * i + j];
    uint2 h[4], l[4];
#pragma unroll
    for (int j = 0; j < 4; j++) split4(f[j], h[j], l[j]);
    ((uint4*)hi)[2 * i]     = make_uint4(h[0].x, h[0].y, h[1].x, h[1].y);
    ((uint4*)hi)[2 * i + 1] = make_uint4(h[2].x, h[2].y, h[3].x, h[3].y);
    ((uint4*)lo)[2 * i]     = make_uint4(l[0].x, l[0].y, l[1].x, l[1].y);
    ((uint4*)lo)[2 * i + 1] = make_uint4(l[2].x, l[2].y, l[3].x, l[3].y);
}
// src [K, nrow]; output 8-col group index = cstep*g + coff within row of ld8 groups.
__global__ void split2d_kernel(const float* __restrict__ src,
                               __nv_bfloat16* __restrict__ hi,
                               __nv_bfloat16* __restrict__ lo,
                               int n8row, int ld8, int cstep, int coff, int nT) {
    int i = blockIdx.x * blockDim.x + threadIdx.x;
    int g = 2 * i;
    int r = g / n8row, c8 = g - r * n8row;
    float4 f[4];
#pragma unroll
    for (int j = 0; j < 4; j++) f[j] = ((const float4*)src)[4 * i + j];
    uint2 h[4], l[4];
#pragma unroll
    for (int j = 0; j < 4; j++) split4(f[j], h[j], l[j]);
    size_t o0 = (size_t)r * ld8 + cstep * c8 + coff;
    size_t o1 = (size_t)r * ld8 + cstep * (c8 + 1) + coff;
    ((uint4*)hi)[o0] = make_uint4(h[0].x, h[0].y, h[1].x, h[1].y);
    ((uint4*)hi)[o1] = make_uint4(h[2].x, h[2].y, h[3].x, h[3].y);
    ((uint4*)lo)[o0] = make_uint4(l[0].x, l[0].y, l[1].x, l[1].y);
    ((uint4*)lo)[o1] = make_uint4(l[2].x, l[2].y, l[3].x, l[3].y);
}
__global__ void splitkv_kernel(const float* __restrict__ Wk,
                               const float* __restrict__ Wv,
                               __nv_bfloat16* __restrict__ hi,
                               __nv_bfloat16* __restrict__ lo, int nT) {
    int i = blockIdx.x * blockDim.x + threadIdx.x;
    int g0 = 2 * i;
    int r  = g0 >> 7;
    int c0 = g0 & 127;
#pragma unroll
    for (int t = 0; t < 2; t++) {
        int c = c0 + t;
        const float* s = (c < 64) ? Wk + (size_t)r * 512 + c * 8
                                  : Wv + (size_t)r * 512 + (c - 64) * 8;
        float4 f0 = ((const float4*)s)[0];
        float4 f1 = ((const float4*)s)[1];
        uint2 h0, l0, h1, l1;
        split4(f0, h0, l0);
        split4(f1, h1, l1);
        size_t o = (size_t)r * (NQKV / 8) + (HID / 8) + c;
        ((uint4*)hi)[o] = make_uint4(h0.x, h0.y, h1.x, h1.y);
        ((uint4*)lo)[o] = make_uint4(l0.x, l0.y, l1.x, l1.y);
    }
}

// ======================= BM=128 GEMM (R9-proven) =======================
#define SST_A_LO 10240u
#define SST_B_HI 20480u
#define SST_B_LO 30208u
#define SSTAGE   39936u
#define SML_SMEM (2 * 39936)

__global__ __launch_bounds__(256, 2)
void gemm_sml_kernel(const __nv_bfloat16* __restrict__ Ahi,
                     const __nv_bfloat16* __restrict__ Alo,
                     const __nv_bfloat16* __restrict__ Whi,
                     const __nv_bfloat16* __restrict__ Wlo,
                     const float* __restrict__ b0, const float* __restrict__ b1,
                     const float* __restrict__ b2, const float* __restrict__ res,
                     float* __restrict__ C, int M, int N, int K) {
    extern __shared__ char sm[];
    const uint32_t smb = smem_u32(sm);
    const int tid  = threadIdx.x;
    const int lane = tid & 31;
    const int warp = tid >> 5;
    const int wm = warp & 3;
    const int wn = warp >> 2;
    const int bm = blockIdx.y * 128;
    const int bn = blockIdx.x * 128;

    const uint32_t aLd = (uint32_t)((wm * 32 + (lane & 15)) * 80 +
                                    ((lane >> 4) & 1) * 16);
    const uint32_t bLd = (uint32_t)((lane & 15) * 304 + (lane >> 4) * 16 +
                                    wn * 128);

    float acc[2][8][4];
#pragma unroll
    for (int i = 0; i < 2; i++)
#pragma unroll
        for (int j = 0; j < 8; j++)
#pragma unroll
            for (int q = 0; q < 4; q++) acc[i][j][q] = 0.f;

    const int nc = K >> 5;

    auto issue = [&](int c, int stg) {
        if (c < nc) {
            const uint32_t st = smb + (uint32_t)stg * SSTAGE;
            const size_t kof = (size_t)c * 32;
#pragma unroll
            for (int i = 0; i < 2; i++) {
                int id = tid + i * 256;
                int r = id >> 2, cc = id & 3;
                uint32_t d = st + (uint32_t)(r * 80 + cc * 16);
                size_t so = (size_t)(bm + r) * K + kof + cc * 8;
                CP16(d, Ahi + so);
                CP16(d + SST_A_LO, Alo + so);
            }
#pragma unroll
            for (int i = 0; i < 2; i++) {
                int id = tid + i * 256;
                int kr = id >> 4, ncc = id & 15;
                uint32_t d = st + SST_B_HI + (uint32_t)(kr * 304 + ncc * 16);
                size_t so = (size_t)(kof + kr) * N + bn + ncc * 8;
                CP16(d, Whi + so);
                CP16(d + 9728u, Wlo + so);
            }
        }
        CP_COMMIT();
    };

    issue(0, 0);

    for (int c = 0; c < nc; c++) {
        asm volatile("cp.async.wait_group 0;" ::: "memory");
        __syncthreads();
        issue(c + 1, (c + 1) & 1);
        const uint32_t sb = smb + (uint32_t)(c & 1) * SSTAGE;
#pragma unroll
        for (int ks = 0; ks < 2; ks++) {
            uint32_t ah[2][4], al[2][4];
#pragma unroll
            for (int tm = 0; tm < 2; tm++) {
                uint32_t off = aLd + (uint32_t)(tm * 16 * 80 + ks * 32);
                ldsm_x4(ah[tm], sb + off);
                ldsm_x4(al[tm], sb + SST_A_LO + off);
            }
            uint32_t bh[2][4], bl[2][4];
            {
                uint32_t off = bLd + (uint32_t)(ks * 16 * 304);
                ldsm_x4t(bh[0], sb + SST_B_HI + off);
                ldsm_x4t(bl[0], sb + SST_B_LO + off);
            }
#pragma unroll
            for (int p = 0; p < 4; p++) {
                const int cur = p & 1, nxt = cur ^ 1;
                if (p < 3) {
                    uint32_t off = bLd + (uint32_t)(ks * 16 * 304 + (p + 1) * 32);
                    ldsm_x4t(bh[nxt], sb + SST_B_HI + off);
                    ldsm_x4t(bl[nxt], sb + SST_B_LO + off);
                }
#pragma unroll
                for (int h = 0; h < 2; h++) {
#pragma unroll
                    for (int tm = 0; tm < 2; tm++) {
                        mma_bf16(acc[tm][p * 2 + h], ah[tm], bh[cur] + 2 * h);
                        mma_bf16(acc[tm][p * 2 + h], ah[tm], bl[cur] + 2 * h);
                        mma_bf16(acc[tm][p * 2 + h], al[tm], bh[cur] + 2 * h);
                    }
                }
            }
        }
    }

#pragma unroll
    for (int tm = 0; tm < 2; tm++) {
#pragma unroll
        for (int bt = 0; bt < 8; bt++) {
            int r0  = bm + wm * 32 + tm * 16 + (lane >> 2);
            int col = bn + wn * 64 + bt * 8 + (lane & 3) * 2;
            float2 v0 = make_float2(acc[tm][bt][0], acc[tm][bt][1]);
            float2 v1 = make_float2(acc[tm][bt][2], acc[tm][bt][3]);
            if (b0) {
                const float* bp; int cc;
                if (col < 2048)      { bp = b0; cc = col; }
                else if (col < 2560) { bp = b1; cc = col - 2048; }
                else                 { bp = b2; cc = col - 2560; }
                float2 bb = *(const float2*)(bp + cc);
                v0.x += bb.x; v0.y += bb.y;
                v1.x += bb.x; v1.y += bb.y;
            }
            if (res) {
                float2 r0v = *(const float2*)(res + (size_t)r0 * N + col);
                float2 r1v = *(const float2*)(res + (size_t)(r0 + 8) * N + col);
                v0.x += r0v.x; v0.y += r0v.y;
                v1.x += r1v.x; v1.y += r1v.y;
            }
            *(float2*)(C + (size_t)r0 * N + col) = v0;
            *(float2*)(C + (size_t)(r0 + 8) * N + col) = v1;
        }
    }
}

// ======================= BM=256 big GEMM (+ optional fused silu epilogue) =======================
#define BST_A_LO 20480u
#define BST_B_HI 40960u
#define BST_B_LO 50688u
#define BSTAGE   60416u
#define BIG_SMEM (3 * 60416)

__global__ __launch_bounds__(512, 1)
void gemm_big_kernel(const __nv_bfloat16* __restrict__ Ahi,
                     const __nv_bfloat16* __restrict__ Alo,
                     const __nv_bfloat16* __restrict__ Whi,
                     const __nv_bfloat16* __restrict__ Wlo,
                     const float* __restrict__ bias, const float* __restrict__ res,
                     float* __restrict__ C,
                     __nv_bfloat16* __restrict__ shi,   // if set: silu-fused plane out
                     __nv_bfloat16* __restrict__ slo,
                     int M, int N, int K) {
    extern __shared__ char sm[];
    const uint32_t smb = smem_u32(sm);
    const int tid  = threadIdx.x;
    const int lane = tid & 31;
    const int warp = tid >> 5;
    const int wm = warp & 7;
    const int wn = warp >> 3;
    const int bm = blockIdx.y * 256;
    const int bn = blockIdx.x * 128;

    const uint32_t aLd = (uint32_t)((wm * 32 + (lane & 15)) * 80 +
                                    ((lane >> 4) & 1) * 16);
    const uint32_t bLd = (uint32_t)((lane & 15) * 304 + (lane >> 4) * 16 +
                                    wn * 128);

    float acc[2][8][4];
#pragma unroll
    for (int i = 0; i < 2; i++)
#pragma unroll
        for (int j = 0; j < 8; j++)
#pragma unroll
            for (int q = 0; q < 4; q++) acc[i][j][q] = 0.f;

    const int nc = K >> 5;

    auto issue = [&](int c, int stg) {
        if (c < nc) {
            const uint32_t st = smb + (uint32_t)stg * BSTAGE;
            const size_t kof = (size_t)c * 32;
#pragma unroll
            for (int i = 0; i < 2; i++) {
                int id = tid + i * 512;
                int r = id >> 2, cc = id & 3;
                uint32_t d = st + (uint32_t)(r * 80 + cc * 16);
                size_t so = (size_t)(bm + r) * K + kof + cc * 8;
                CP16(d, Ahi + so);
                CP16(d + BST_A_LO, Alo + so);
            }
            {
                int kr = tid >> 4, ncc = tid & 15;
                uint32_t d = st + BST_B_HI + (uint32_t)(kr * 304 + ncc * 16);
                size_t so = (size_t)(kof + kr) * N + bn + ncc * 8;
                CP16(d, Whi + so);
                CP16(d + 9728u, Wlo + so);
            }
        }
        CP_COMMIT();
    };

    issue(0, 0);
    issue(1, 1);

    for (int c = 0; c < nc; c++) {
        asm volatile("cp.async.wait_group 1;" ::: "memory");
        __syncthreads();
        issue(c + 2, (c + 2) % 3);
        const uint32_t sb = smb + (uint32_t)(c % 3) * BSTAGE;
#pragma unroll
        for (int ks = 0; ks < 2; ks++) {
            uint32_t ah[2][4], al[2][4];
#pragma unroll
            for (int tm = 0; tm < 2; tm++) {
                uint32_t off = aLd + (uint32_t)(tm * 16 * 80 + ks * 32);
                ldsm_x4(ah[tm], sb + off);
                ldsm_x4(al[tm], sb + BST_A_LO + off);
            }
            uint32_t bh[2][4], bl[2][4];
            {
                uint32_t off = bLd + (uint32_t)(ks * 16 * 304);
                ldsm_x4t(bh[0], sb + BST_B_HI + off);
                ldsm_x4t(bl[0], sb + BST_B_LO + off);
            }
#pragma unroll
            for (int p = 0; p < 4; p++) {
                const int cur = p & 1, nxt = cur ^ 1;
                if (p < 3) {
                    uint32_t off = bLd + (uint32_t)(ks * 16 * 304 + (p + 1) * 32);
                    ldsm_x4t(bh[nxt], sb + BST_B_HI + off);
                    ldsm_x4t(bl[nxt], sb + BST_B_LO + off);
                }
#pragma unroll
                for (int h = 0; h < 2; h++) {
#pragma unroll
                    for (int tm = 0; tm < 2; tm++) {
                        mma_bf16(acc[tm][p * 2 + h], ah[tm], bh[cur] + 2 * h);
                        mma_bf16(acc[tm][p * 2 + h], ah[tm], bl[cur] + 2 * h);
                        mma_bf16(acc[tm][p * 2 + h], al[tm], bh[cur] + 2 * h);
                    }
                }
            }
        }
    }

    if (shi) {
        // fused SiLU(gate)*up epilogue: acc[tm][2t]=gate, acc[tm][2t+1]=up for
        // logical cols colL..colL+1; output planes have row stride N/2.
        const int NL = N >> 1;
#pragma unroll
        for (int tm = 0; tm < 2; tm++) {
#pragma unroll
            for (int t = 0; t < 4; t++) {
                int r0   = bm + wm * 32 + tm * 16 + (lane >> 2);
                int colL = (bn >> 1) + wn * 32 + t * 8 + (lane & 3) * 2;
                float* gt = acc[tm][2 * t];
                float* up = acc[tm][2 * t + 1];
                float o0 = silu(gt[0]) * up[0];
                float o1 = silu(gt[1]) * up[1];
                float o2 = silu(gt[2]) * up[2];
                float o3 = silu(gt[3]) * up[3];
                uint32_t hA, lA, hB, lB;
                hA = splitpack(o0, o1, lA);
                hB = splitpack(o2, o3, lB);
                size_t iA = ((size_t)r0 * NL + colL) >> 1;
                size_t iB = ((size_t)(r0 + 8) * NL + colL) >> 1;
                ((uint32_t*)shi)[iA] = hA;
                ((uint32_t*)slo)[iA] = lA;
                ((uint32_t*)shi)[iB] = hB;
                ((uint32_t*)slo)[iB] = lB;
            }
        }
        return;
    }

#pragma unroll
    for (int tm = 0; tm < 2; tm++) {
#pragma unroll
        for (int bt = 0; bt < 8; bt++) {
            int r0  = bm + wm * 32 + tm * 16 + (lane >> 2);
            int col = bn + wn * 64 + bt * 8 + (lane & 3) * 2;
            float2 v0 = make_float2(acc[tm][bt][0], acc[tm][bt][1]);
            float2 v1 = make_float2(acc[tm][bt][2], acc[tm][bt][3]);
            if (bias) {
                float2 bb = *(const float2*)(bias + col);
                v0.x += bb.x; v0.y += bb.y;
                v1.x += bb.x; v1.y += bb.y;
            }
            if (res) {
                float2 r0v = *(const float2*)(res + (size_t)r0 * N + col);
                float2 r1v = *(const float2*)(res + (size_t)(r0 + 8) * N + col);
                v0.x += r0v.x; v0.y += r0v.y;
                v1.x += r1v.x; v1.y += r1v.y;
            }
            *(float2*)(C + (size_t)r0 * N + col) = v0;
            *(float2*)(C + (size_t)(r0 + 8) * N + col) = v1;
        }
    }
}

// ---------------- RMSNorm -> bf16 hi/lo planes (optional embed gather) ----------------
__global__ void rmsnorm_split_kernel(const float* __restrict__ x,
                                     const int* __restrict__ ids,
                                     const float* __restrict__ emb,
                                     const float* __restrict__ w,
                                     float* __restrict__ hout,
                                     __nv_bfloat16* __restrict__ hi,
                                     __nv_bfloat16* __restrict__ lo) {
    int row = blockIdx.x;
    const float4* xr;
    if (ids) {
        int tok = ids[row];
        xr = (const float4*)(emb + (size_t)tok * HID);
    } else {
        xr = (const float4*)(x + (size_t)row * HID);
    }
    const float4* wr = (const float4*)w;

    float4 v0 = xr[threadIdx.x];
    float4 v1 = xr[threadIdx.x + 256];
    if (hout) {
        ((float4*)(hout + (size_t)row * HID))[threadIdx.x] = v0;
        ((float4*)(hout + (size_t)row * HID))[threadIdx.x + 256] = v1;
    }
    float ss = v0.x * v0.x + v0.y * v0.y + v0.z * v0.z + v0.w * v0.w
             + v1.x * v1.x + v1.y * v1.y + v1.z * v1.z + v1.w * v1.w;

    __shared__ float red[8];
    for (int o = 16; o > 0; o >>= 1) ss += __shfl_down_sync(0xffffffffu, ss, o);
    if ((threadIdx.x & 31) == 0) red[threadIdx.x >> 5] = ss;
    __syncthreads();
    if (threadIdx.x < 8) {
        float t = red[threadIdx.x];
        for (int o = 4; o > 0; o >>= 1) t += __shfl_down_sync(0xffu, t, o);
        if (threadIdx.x == 0) red[0] = t;
    }
    __syncthreads();
    float inv = rsqrtf(red[0] / (float)HID + 1e-6f);

    float4 w0 = wr[threadIdx.x];
    float4 w1 = wr[threadIdx.x + 256];
    float4 o0, o1;
    o0.x = v0.x * inv * w0.x; o0.y = v0.y * inv * w0.y;
    o0.z = v0.z * inv * w0.z; o0.w = v0.w * inv * w0.w;
    o1.x = v1.x * inv * w1.x; o1.y = v1.y * inv * w1.y;
    o1.z = v1.z * inv * w1.z; o1.w = v1.w * inv * w1.w;
    uint2 h, l;
    size_t b = (size_t)row * (HID / 4);
    split4(o0, h, l);
    ((uint2*)hi)[b + threadIdx.x] = h;
    ((uint2*)lo)[b + threadIdx.x] = l;
    split4(o1, h, l);
    ((uint2*)hi)[b + threadIdx.x + 256] = h;
    ((uint2*)lo)[b + threadIdx.x + 256] = l;
}

// ---------------- RoPE: fp32 qkv -> rotated bf16 hi/lo planes ----------------
__global__ void rope_split_kernel(const float* __restrict__ qkv,
                                  __nv_bfloat16* __restrict__ hi,
                                  __nv_bfloat16* __restrict__ lo) {
    int s = blockIdx.x;
    int hh = blockIdx.y;
    int i = threadIdx.x;
    size_t base = (size_t)s * NQKV +
        ((hh < NHEAD) ? hh * HDIM
         : (hh < NHEAD + NKVH) ? HID + (hh - NHEAD) * HDIM
         : HID + NKVH * HDIM + (hh - NHEAD - NKVH) * HDIM);
    float x1 = qkv[base + i];
    float x2 = qkv[base + i + 64];
    float y1, y2;
    if (hh < NHEAD + NKVH) {
        float inv = powf(1000000.0f, -(float)i / 64.0f);
        float f = (float)s * inv;
        float c = cosf(f), sn = sinf(f);
        y1 = x1 * c - x2 * sn;
        y2 = x2 * c + x1 * sn;
    } else {
        y1 = x1; y2 = x2;
    }
    uint16_t h1, l1, h2, l2;
    split1(y1, h1, l1);
    split1(y2, h2, l2);
    ((uint16_t*)hi)[base + i]      = h1;
    ((uint16_t*)lo)[base + i]      = l1;
    ((uint16_t*)hi)[base + i + 64] = h2;
    ((uint16_t*)lo)[base + i + 64] = l2;
}

// ---------------- tensor-core flash attention (bf16x3, causal, GQA) ----------------
#define ATT_STRIDE 136
#define ATT_PLANE  (64 * ATT_STRIDE * 2)
#define ATT_SMEM   (6 * ATT_PLANE)

__global__ __launch_bounds__(128) void attn_mma_kernel(
    const __nv_bfloat16* __restrict__ qhi, const __nv_bfloat16* __restrict__ qlo,
    __nv_bfloat16* __restrict__ ohi, __nv_bfloat16* __restrict__ olo) {
    extern __shared__ char smc[];
    const uint32_t smb = smem_u32(smc);
    const uint32_t Qh = smb,            Ql = Qh + ATT_PLANE;
    const uint32_t Kh = Ql + ATT_PLANE, Kl = Kh + ATT_PLANE;
    const uint32_t Vh = Kl + ATT_PLANE, Vl = Vh + ATT_PLANE;

    const int head = blockIdx.x;
    const int qb   = blockIdx.y;
    const int kvh  = head >> 2;
    const int tid  = threadIdx.x;
    const int lane = tid & 31;
    const int warp = tid >> 5;

#pragma unroll
    for (int i = 0; i < 8; i++) {
        int id = tid + i * 128;
        int r = id >> 4, c = id & 15;
        uint32_t d = (uint32_t)(r * ATT_STRIDE * 2 + c * 16);
        size_t so = (size_t)(qb * 64 + r) * NQKV + head * HDIM + c * 8;
        CP16(Qh + d, qhi + so);
        CP16(Ql + d, qlo + so);
    }
    CP_COMMIT();

    float o[16][4];
#pragma unroll
    for (int t = 0; t < 16; t++)
#pragma unroll
        for (int q = 0; q < 4; q++) o[t][q] = 0.f;
    float mA = -1e30f, mB = -1e30f, lA = 0.f, lB = 0.f;

    const uint32_t qLd = (uint32_t)((warp * 16 + (lane & 15)) * ATT_STRIDE * 2 +
                                    ((lane >> 4) & 1) * 16);
    const uint32_t kLd = (uint32_t)((lane & 7) * ATT_STRIDE * 2 +
                                    ((lane >> 3) & 1) * 16);
    const uint32_t vLd = (uint32_t)((lane & 15) * ATT_STRIDE * 2 +
                                    ((lane >> 4) & 1) * 16);
    const float scale = 0.08838834764831845f;
    const int rowA = warp * 16 + (lane >> 2);
    const int rowB = rowA + 8;

    for (int kb = 0; kb <= qb; kb++) {
        __syncthreads();
#pragma unroll
        for (int i = 0; i < 8; i++) {
            int id = tid + i * 128;
            int r = id >> 4, c = id & 15;
            uint32_t d = (uint32_t)(r * ATT_STRIDE * 2 + c * 16);
            size_t ko = (size_t)(kb * 64 + r) * NQKV + HID + kvh * HDIM + c * 8;
            size_t vo = ko + NKVH * HDIM;
            CP16(Kh + d, qhi + ko);
            CP16(Kl + d, qlo + ko);
            CP16(Vh + d, qhi + vo);
            CP16(Vl + d, qlo + vo);
        }
        CP_COMMIT();
        asm volatile("cp.async.wait_group 0;" ::: "memory");
        __syncthreads();

        float s[8][4];
#pragma unroll
        for (int t = 0; t < 8; t++)
#pragma unroll
            for (int q = 0; q < 4; q++) s[t][q] = 0.f;
#pragma unroll
        for (int ds = 0; ds < 8; ds++) {
            uint32_t ah[4], al[4];
            ldsm_x4(ah, Qh + qLd + ds * 32);
            ldsm_x4(al, Ql + qLd + ds * 32);
#pragma unroll
            for (int nt = 0; nt < 8; nt++) {
                uint32_t ko = kLd + (uint32_t)(nt * 8 * ATT_STRIDE * 2 + ds * 32);
                uint32_t bh[2], bl[2];
                ldsm_x2(bh, Kh + ko);
                ldsm_x2(bl, Kl + ko);
                mma_bf16(s[nt], ah, bh);
                mma_bf16(s[nt], ah, bl);
                mma_bf16(s[nt], al, bh);
            }
        }

#pragma unroll
        for (int nt = 0; nt < 8; nt++) {
#pragma unroll
            for (int q = 0; q < 4; q++) s[nt][q] *= scale;
            if (kb == qb) {
                int c0 = nt * 8 + (lane & 3) * 2;
                if (c0 > rowA)     s[nt][0] = -1e9f;
                if (c0 + 1 > rowA) s[nt][1] = -1e9f;
                if (c0 > rowB)     s[nt][2] = -1e9f;
                if (c0 + 1 > rowB) s[nt][3] = -1e9f;
            }
        }

        float mxA = -1e30f, mxB = -1e30f;
#pragma unroll
        for (int nt = 0; nt < 8; nt++) {
            mxA = fmaxf(mxA, fmaxf(s[nt][0], s[nt][1]));
            mxB = fmaxf(mxB, fmaxf(s[nt][2], s[nt][3]));
        }
        mxA = fmaxf(mxA, __shfl_xor_sync(0xffffffffu, mxA, 1));
        mxA = fmaxf(mxA, __shfl_xor_sync(0xffffffffu, mxA, 2));
        mxB = fmaxf(mxB, __shfl_xor_sync(0xffffffffu, mxB, 1));
        mxB = fmaxf(mxB, __shfl_xor_sync(0xffffffffu, mxB, 2));
        float mAn = fmaxf(mA, mxA), mBn = fmaxf(mB, mxB);
        float aAf = expf(mA - mAn), aBf = expf(mB - mBn);
        float pA = 0.f, pB = 0.f;
#pragma unroll
        for (int nt = 0; nt < 8; nt++) {
            s[nt][0] = expf(s[nt][0] - mAn);
            s[nt][1] = expf(s[nt][1] - mAn);
            s[nt][2] = expf(s[nt][2] - mBn);
            s[nt][3] = expf(s[nt][3] - mBn);
            pA += s[nt][0] + s[nt][1];
            pB += s[nt][2] + s[nt][3];
        }
        pA += __shfl_xor_sync(0xffffffffu, pA, 1);
        pA += __shfl_xor_sync(0xffffffffu, pA, 2);
        pB += __shfl_xor_sync(0xffffffffu, pB, 1);
        pB += __shfl_xor_sync(0xffffffffu, pB, 2);
        lA = lA * aAf + pA;
        lB = lB * aBf + pB;
        mA = mAn;
        mB = mBn;
#pragma unroll
        for (int t = 0; t < 16; t++) {
            o[t][0] *= aAf; o[t][1] *= aAf;
            o[t][2] *= aBf; o[t][3] *= aBf;
        }

#pragma unroll
        for (int ks = 0; ks < 4; ks++) {
            uint32_t ph[4], pl[4];
            ph[0] = splitpack(s[2 * ks][0],     s[2 * ks][1],     pl[0]);
            ph[1] = splitpack(s[2 * ks][2],     s[2 * ks][3],     pl[1]);
            ph[2] = splitpack(s[2 * ks + 1][0], s[2 * ks + 1][1], pl[2]);
            ph[3] = splitpack(s[2 * ks + 1][2], s[2 * ks + 1][3], pl[3]);
#pragma unroll
            for (int dt = 0; dt < 8; dt++) {
                uint32_t vo = vLd + (uint32_t)(ks * 16 * ATT_STRIDE * 2 + dt * 32);
                uint32_t vh[4], vl[4];
                ldsm_x4t(vh, Vh + vo);
                ldsm_x4t(vl, Vl + vo);
#pragma unroll
                for (int h = 0; h < 2; h++) {
                    float* od = o[dt * 2 + h];
                    mma_bf16(od, ph, vh + 2 * h);
                    mma_bf16(od, ph, vl + 2 * h);
                    mma_bf16(od, pl, vh + 2 * h);
                }
            }
        }
    }

    float liA = 1.0f / lA, liB = 1.0f / lB;
    int gRowA = qb * 64 + rowA;
    int gRowB = qb * 64 + rowB;
#pragma unroll
    for (int nt = 0; nt < 16; nt++) {
        int col = head * HDIM + nt * 8 + (lane & 3) * 2;
        uint32_t hA, lAo, hB, lBo;
        hA = splitpack(o[nt][0] * liA, o[nt][1] * liA, lAo);
        hB = splitpack(o[nt][2] * liB, o[nt][3] * liB, lBo);
        size_t iA = ((size_t)gRowA * HID + col) >> 1;
        size_t iB = ((size_t)gRowB * HID + col) >> 1;
        ((uint32_t*)ohi)[iA] = hA;
        ((uint32_t*)olo)[iA] = lAo;
        ((uint32_t*)ohi)[iB] = hB;
        ((uint32_t*)olo)[iB] = lBo;
    }
}

// ---------------- host orchestration ----------------
static __nv_bfloat16 *s_ahi, *s_alo, *s_fhi, *s_flo, *s_whi, *s_wlo,
                     *s_qhi, *s_qlo;

static void run_split(const float* src, size_t n) {
    int nT = (int)(n / 16);
    split_kernel<<<nT / 256, 256>>>(src, s_whi, s_wlo, nT);
}

extern "C" void kernel_launch(void* const* d_in, const int* in_sizes, int n_in,
                              void* d_out, int out_size) {
    const int*   ids    = (const int*)d_in[0];
    const float* emb    = (const float*)d_in[1];
    const float* Wq     = (const float*)d_in[2];
    const float* bq     = (const float*)d_in[3];
    const float* Wk     = (const float*)d_in[4];
    const float* bk     = (const float*)d_in[5];
    const float* Wv     = (const float*)d_in[6];
    const float* bv     = (const float*)d_in[7];
    const float* Wo     = (const float*)d_in[8];
    const float* ln1    = (const float*)d_in[9];
    const float* ln2    = (const float*)d_in[10];
    const float* Wg     = (const float*)d_in[11];
    const float* Wu     = (const float*)d_in[12];
    const float* Wd     = (const float*)d_in[13];
    const float* norm_w = (const float*)d_in[14];
    const float* Wlm    = (const float*)d_in[15];
    const float* blm    = (const float*)d_in[16];
    float* out = (float*)d_out;

    float* base = nullptr;
    cudaGetSymbolAddress((void**)&base, g_scratch);
    cudaGetSymbolAddress((void**)&s_ahi, g_ahi);
    cudaGetSymbolAddress((void**)&s_alo, g_alo);
    cudaGetSymbolAddress((void**)&s_fhi, g_fhi);
    cudaGetSymbolAddress((void**)&s_flo, g_flo);
    cudaGetSymbolAddress((void**)&s_whi, g_whi);
    cudaGetSymbolAddress((void**)&s_wlo, g_wlo);
    cudaGetSymbolAddress((void**)&s_qhi, g_qkvhi);
    cudaGetSymbolAddress((void**)&s_qlo, g_qkvlo);

    float* hbuf  = base;
    float* qkv   = base + (size_t)SH;

    cudaFuncSetAttribute(attn_mma_kernel,
                         cudaFuncAttributeMaxDynamicSharedMemorySize, ATT_SMEM);
    cudaFuncSetAttribute(gemm_sml_kernel,
                         cudaFuncAttributeMaxDynamicSharedMemorySize, SML_SMEM);
    cudaFuncSetAttribute(gemm_big_kernel,
                         cudaFuncAttributeMaxDynamicSharedMemorySize, BIG_SMEM);

    for (int l = 0; l < NLAYER; l++) {
        const float* Wql = Wq + (size_t)l * HID * HID;
        const float* bql = bq + (size_t)l * HID;
        const float* Wkl = Wk + (size_t)l * HID * (NKVH * HDIM);
        const float* bkl = bk + (size_t)l * (NKVH * HDIM);
        const float* Wvl = Wv + (size_t)l * HID * (NKVH * HDIM);
        const float* bvl = bv + (size_t)l * (NKVH * HDIM);
        const float* Wol = Wo + (size_t)l * HID * HID;
        const float* l1  = ln1 + (size_t)l * HID;
        const float* l2  = ln2 + (size_t)l * HID;
        const float* Wgl = Wg + (size_t)l * HID * FFD;
        const float* Wul = Wu + (size_t)l * HID * FFD;
        const float* Wdl = Wd + (size_t)l * FFD * HID;

        // ---- fused QKV projection ----
        {
            int nT = (int)((size_t)HID * HID / 16);
            split2d_kernel<<<nT / 256, 256>>>(
                Wql, s_whi, s_wlo, HID / 8, NQKV / 8, 1, 0, nT);
        }
        {
            int nT = HID * 1024 / 16;
            splitkv_kernel<<<nT / 256, 256>>>(Wkl, Wvl, s_whi, s_wlo, nT);
        }
        if (l == 0)
            rmsnorm_split_kernel<<<SQ, 256>>>(nullptr, ids, emb, l1, hbuf,
                                              s_ahi, s_alo);
        else
            rmsnorm_split_kernel<<<SQ, 256>>>(hbuf, nullptr, nullptr, l1,
                                              nullptr, s_ahi, s_alo);
        {
            dim3 grid(NQKV / 128, SQ / 128);
            gemm_sml_kernel<<<grid, 256, SML_SMEM>>>(
                s_ahi, s_alo, s_whi, s_wlo, bql, bkl, bvl, nullptr, qkv,
                SQ, NQKV, HID);
        }

        // ---- RoPE + split ----
        dim3 rgrid(SQ, NHEAD + 2 * NKVH);
        rope_split_kernel<<<rgrid, 64>>>(qkv, s_qhi, s_qlo);

        // ---- attention -> activation planes ----
        dim3 agrid(NHEAD, SQ / 64);
        attn_mma_kernel<<<agrid, 128, ATT_SMEM>>>(s_qhi, s_qlo, s_ahi, s_alo);

        // ---- O projection (+residual) ----
        run_split(Wol, (size_t)HID * HID);
        {
            dim3 grid(HID / 128, SQ / 128);
            gemm_sml_kernel<<<grid, 256, SML_SMEM>>>(
                s_ahi, s_alo, s_whi, s_wlo, nullptr, nullptr, nullptr, hbuf,
                hbuf, SQ, HID, HID);
        }

        // ---- FF: fused gate|up (interleaved) with silu epilogue ----
        rmsnorm_split_kernel<<<SQ, 256>>>(hbuf, nullptr, nullptr, l2,
                                          nullptr, s_ahi, s_alo);
        {
            int nT = (int)((size_t)HID * FFD / 16);
            split2d_kernel<<<nT / 256, 256>>>(
                Wgl, s_whi, s_wlo, FFD / 8, NFF2 / 8, 2, 0, nT);
            split2d_kernel<<<nT / 256, 256>>>(
                Wul, s_whi, s_wlo, FFD / 8, NFF2 / 8, 2, 1, nT);
        }
        {
            dim3 grid(NFF2 / 128, SQ / 256);
            gemm_big_kernel<<<grid, 512, BIG_SMEM>>>(
                s_ahi, s_alo, s_whi, s_wlo, nullptr, nullptr, nullptr,
                s_fhi, s_flo, SQ, NFF2, HID);
        }
        // ---- down projection (+residual) ----
        run_split(Wdl, (size_t)FFD * HID);
        {
            dim3 grid(HID / 128, SQ / 256);
            gemm_big_kernel<<<grid, 512, BIG_SMEM>>>(
                s_fhi, s_flo, s_whi, s_wlo, nullptr, hbuf, hbuf,
                nullptr, nullptr, SQ, HID, FFD);
        }
    }

    rmsnorm_split_kernel<<<SQ, 256>>>(hbuf, nullptr, nullptr, norm_w,
                                      nullptr, s_ahi, s_alo);
    run_split(Wlm, (size_t)HID * VOC);
    {
        dim3 grid(VOC / 128, SQ / 256);
        gemm_big_kernel<<<grid, 512, BIG_SMEM>>>(
            s_ahi, s_alo, s_whi, s_wlo, blm, nullptr, out,
            nullptr, nullptr, SQ, VOC, HID);
    }
}

// round 14
// speedup vs baseline: 1.0229x; 1.0229x over previous
#include <cuda_runtime.h>
#include <cuda_bf16.h>
#include <math.h>
#include <cstdint>

// ---------------- problem constants ----------------
#define SQ     2048
#define HID    2048
#define VOC    32000
#define NHEAD  16
#define NKVH   4
#define HDIM   128
#define FFD    8192
#define NLAYER 4
#define NQKV   3072   // 2048 + 512 + 512
#define NFF2   16384  // fused gate|up, 32-col interleaved

#define SH  (SQ * HID)
#define SFF (SQ * FFD)

__device__ float g_scratch[(size_t)SH + (size_t)SQ * NQKV];
__device__ __nv_bfloat16 g_ahi[(size_t)SFF];
__device__ __nv_bfloat16 g_alo[(size_t)SFF];
__device__ __nv_bfloat16 g_fhi[(size_t)SFF];
__device__ __nv_bfloat16 g_flo[(size_t)SFF];
__device__ __nv_bfloat16 g_whi[(size_t)HID * VOC];
__device__ __nv_bfloat16 g_wlo[(size_t)HID * VOC];
__device__ __nv_bfloat16 g_qkvhi[(size_t)SQ * NQKV];
__device__ __nv_bfloat16 g_qkvlo[(size_t)SQ * NQKV];

// ======================= helpers =======================
__device__ __forceinline__ uint32_t smem_u32(const void* p) {
    uint32_t a;
    asm("{ .reg .u64 t; cvta.to.shared.u64 t, %1; cvt.u32.u64 %0, t; }"
        : "=r"(a) : "l"(p));
    return a;
}
__device__ __forceinline__ void ldsm_x4(uint32_t* r, uint32_t addr) {
    asm volatile("ldmatrix.sync.aligned.m8n8.x4.shared.b16 {%0,%1,%2,%3}, [%4];"
                 : "=r"(r[0]), "=r"(r[1]), "=r"(r[2]), "=r"(r[3]) : "r"(addr));
}
__device__ __forceinline__ void ldsm_x2(uint32_t* r, uint32_t addr) {
    asm volatile("ldmatrix.sync.aligned.m8n8.x2.shared.b16 {%0,%1}, [%2];"
                 : "=r"(r[0]), "=r"(r[1]) : "r"(addr));
}
__device__ __forceinline__ void ldsm_x4t(uint32_t* r, uint32_t addr) {
    asm volatile("ldmatrix.sync.aligned.m8n8.x4.trans.shared.b16 {%0,%1,%2,%3}, [%4];"
                 : "=r"(r[0]), "=r"(r[1]), "=r"(r[2]), "=r"(r[3]) : "r"(addr));
}
__device__ __forceinline__ void mma_bf16(float* c, const uint32_t* a,
                                         const uint32_t* b) {
    asm volatile("mma.sync.aligned.m16n8k16.row.col.f32.bf16.bf16.f32 "
                 "{%0,%1,%2,%3}, {%4,%5,%6,%7}, {%8,%9}, {%0,%1,%2,%3};"
                 : "+f"(c[0]), "+f"(c[1]), "+f"(c[2]), "+f"(c[3])
                 : "r"(a[0]), "r"(a[1]), "r"(a[2]), "r"(a[3]),
                   "r"(b[0]), "r"(b[1]));
}
__device__ __forceinline__ uint32_t pack2(__nv_bfloat16 a, __nv_bfloat16 b) {
    uint16_t ua = *(uint16_t*)&a, ub = *(uint16_t*)&b;
    return ((uint32_t)ub << 16) | (uint32_t)ua;
}
__device__ __forceinline__ void split4(float4 f, uint2& hi, uint2& lo) {
    __nv_bfloat16 hx = __float2bfloat16_rn(f.x);
    __nv_bfloat16 hy = __float2bfloat16_rn(f.y);
    __nv_bfloat16 hz = __float2bfloat16_rn(f.z);
    __nv_bfloat16 hw = __float2bfloat16_rn(f.w);
    __nv_bfloat16 lx = __float2bfloat16_rn(f.x - __bfloat162float(hx));
    __nv_bfloat16 ly = __float2bfloat16_rn(f.y - __bfloat162float(hy));
    __nv_bfloat16 lz = __float2bfloat16_rn(f.z - __bfloat162float(hz));
    __nv_bfloat16 lw = __float2bfloat16_rn(f.w - __bfloat162float(hw));
    hi = make_uint2(pack2(hx, hy), pack2(hz, hw));
    lo = make_uint2(pack2(lx, ly), pack2(lz, lw));
}
__device__ __forceinline__ void split1(float x, uint16_t& h, uint16_t& l) {
    __nv_bfloat16 hb = __float2bfloat16_rn(x);
    __nv_bfloat16 lb = __float2bfloat16_rn(x - __bfloat162float(hb));
    h = *(uint16_t*)&hb;
    l = *(uint16_t*)&lb;
}
__device__ __forceinline__ uint32_t splitpack(float a, float b, uint32_t& lo) {
    uint16_t ha, la, hb, lb;
    split1(a, ha, la);
    split1(b, hb, lb);
    lo = ((uint32_t)lb << 16) | la;
    return ((uint32_t)hb << 16) | ha;
}
__device__ __forceinline__ float silu_f(float x) {
    return x / (1.f + expf(-x));
}
#define CP16(dst, src) \
    asm volatile("cp.async.cg.shared.global [%0], [%1], 16;" :: "r"(dst), "l"(src))
#define CP_COMMIT() asm volatile("cp.async.commit_group;" ::: "memory")

// ---------------- weight splits ----------------
__global__ void split_kernel(const float* __restrict__ src,
                             __nv_bfloat16* __restrict__ hi,
                             __nv_bfloat16* __restrict__ lo, int nT) {
    int i = blockIdx.x * blockDim.x + threadIdx.x;
    float4 f[4];
#pragma unroll
    for (int j = 0; j < 4; j++) f[j] = ((const float4*)src)[4 * i + j];
    uint2 h[4], l[4];
#pragma unroll
    for (int j = 0; j < 4; j++) split4(f[j], h[j], l[j]);
    ((uint4*)hi)[2 * i]     = make_uint4(h[0].x, h[0].y, h[1].x, h[1].y);
    ((uint4*)hi)[2 * i + 1] = make_uint4(h[2].x, h[2].y, h[3].x, h[3].y);
    ((uint4*)lo)[2 * i]     = make_uint4(l[0].x, l[0].y, l[1].x, l[1].y);
    ((uint4*)lo)[2 * i + 1] = make_uint4(l[2].x, l[2].y, l[3].x, l[3].y);
}
// src [K, nrow] -> planes with row stride ld8*8 elems (R12-proven contiguous)
__global__ void split2d_kernel(const float* __restrict__ src,
                               __nv_bfloat16* __restrict__ hi,
                               __nv_bfloat16* __restrict__ lo,
                               int n8row, int ld8, int nT) {
    int i = blockIdx.x * blockDim.x + threadIdx.x;
    int g = 2 * i;
    int r = g / n8row, c8 = g - r * n8row;
    float4 f[4];
#pragma unroll
    for (int j = 0; j < 4; j++) f[j] = ((const float4*)src)[4 * i + j];
    uint2 h[4], l[4];
#pragma unroll
    for (int j = 0; j < 4; j++) split4(f[j], h[j], l[j]);
    size_t o = (size_t)r * ld8 + c8;
    ((uint4*)hi)[o]     = make_uint4(h[0].x, h[0].y, h[1].x, h[1].y);
    ((uint4*)hi)[o + 1] = make_uint4(h[2].x, h[2].y, h[3].x, h[3].y);
    ((uint4*)lo)[o]     = make_uint4(l[0].x, l[0].y, l[1].x, l[1].y);
    ((uint4*)lo)[o + 1] = make_uint4(l[2].x, l[2].y, l[3].x, l[3].y);
}
__global__ void splitkv_kernel(const float* __restrict__ Wk,
                               const float* __restrict__ Wv,
                               __nv_bfloat16* __restrict__ hi,
                               __nv_bfloat16* __restrict__ lo, int nT) {
    int i = blockIdx.x * blockDim.x + threadIdx.x;
    int g0 = 2 * i;
    int r  = g0 >> 7;
    int c0 = g0 & 127;
#pragma unroll
    for (int t = 0; t < 2; t++) {
        int c = c0 + t;
        const float* s = (c < 64) ? Wk + (size_t)r * 512 + c * 8
                                  : Wv + (size_t)r * 512 + (c - 64) * 8;
        float4 f0 = ((const float4*)s)[0];
        float4 f1 = ((const float4*)s)[1];
        uint2 h0, l0, h1, l1;
        split4(f0, h0, l0);
        split4(f1, h1, l1);
        size_t o = (size_t)r * (NQKV / 8) + (HID / 8) + c;
        ((uint4*)hi)[o] = make_uint4(h0.x, h0.y, h1.x, h1.y);
        ((uint4*)lo)[o] = make_uint4(l0.x, l0.y, l1.x, l1.y);
    }
}
// merged gate|up split, 32-col interleave, fully coalesced both sides.
// Output plane: [HID rows x 2048 groups]; unit u = pg>>2; even=gate, odd=up;
// logical group lg = (u>>1)*4 + (pg&3).
__global__ void splitgu_kernel(const float* __restrict__ Wg,
                               const float* __restrict__ Wu,
                               __nv_bfloat16* __restrict__ hi,
                               __nv_bfloat16* __restrict__ lo, int nT) {
    int i = blockIdx.x * blockDim.x + threadIdx.x;
    int G = 2 * i;                        // physical group index (even)
    int r  = G >> 11;                     // 2048 groups per row
    int pg = G & 2047;
    int u  = pg >> 2;
    int lg = (u >> 1) * 4 + (pg & 3);
    const float* src = ((u & 1) ? Wu : Wg) + (size_t)r * FFD + lg * 8;
    float4 f[4];
#pragma unroll
    for (int j = 0; j < 4; j++) f[j] = ((const float4*)src)[j];
    uint2 h[4], l[4];
#pragma unroll
    for (int j = 0; j < 4; j++) split4(f[j], h[j], l[j]);
    size_t o = (size_t)r * 2048 + pg;
    ((uint4*)hi)[o]     = make_uint4(h[0].x, h[0].y, h[1].x, h[1].y);
    ((uint4*)hi)[o + 1] = make_uint4(h[2].x, h[2].y, h[3].x, h[3].y);
    ((uint4*)lo)[o]     = make_uint4(l[0].x, l[0].y, l[1].x, l[1].y);
    ((uint4*)lo)[o + 1] = make_uint4(l[2].x, l[2].y, l[3].x, l[3].y);
}

// ======================= BM=128 GEMM (R9-proven) =======================
#define SST_A_LO 10240u
#define SST_B_HI 20480u
#define SST_B_LO 30208u
#define SSTAGE   39936u
#define SML_SMEM (2 * 39936)

__global__ __launch_bounds__(256, 2)
void gemm_sml_kernel(const __nv_bfloat16* __restrict__ Ahi,
                     const __nv_bfloat16* __restrict__ Alo,
                     const __nv_bfloat16* __restrict__ Whi,
                     const __nv_bfloat16* __restrict__ Wlo,
                     const float* __restrict__ b0, const float* __restrict__ b1,
                     const float* __restrict__ b2, const float* __restrict__ res,
                     float* __restrict__ C, int M, int N, int K) {
    extern __shared__ char sm[];
    const uint32_t smb = smem_u32(sm);
    const int tid  = threadIdx.x;
    const int lane = tid & 31;
    const int warp = tid >> 5;
    const int wm = warp & 3;
    const int wn = warp >> 2;
    const int bm = blockIdx.y * 128;
    const int bn = blockIdx.x * 128;

    const uint32_t aLd = (uint32_t)((wm * 32 + (lane & 15)) * 80 +
                                    ((lane >> 4) & 1) * 16);
    const uint32_t bLd = (uint32_t)((lane & 15) * 304 + (lane >> 4) * 16 +
                                    wn * 128);

    float acc[2][8][4];
#pragma unroll
    for (int i = 0; i < 2; i++)
#pragma unroll
        for (int j = 0; j < 8; j++)
#pragma unroll
            for (int q = 0; q < 4; q++) acc[i][j][q] = 0.f;

    const int nc = K >> 5;

    auto issue = [&](int c, int stg) {
        if (c < nc) {
            const uint32_t st = smb + (uint32_t)stg * SSTAGE;
            const size_t kof = (size_t)c * 32;
#pragma unroll
            for (int i = 0; i < 2; i++) {
                int id = tid + i * 256;
                int r = id >> 2, cc = id & 3;
                uint32_t d = st + (uint32_t)(r * 80 + cc * 16);
                size_t so = (size_t)(bm + r) * K + kof + cc * 8;
                CP16(d, Ahi + so);
                CP16(d + SST_A_LO, Alo + so);
            }
#pragma unroll
            for (int i = 0; i < 2; i++) {
                int id = tid + i * 256;
                int kr = id >> 4, ncc = id & 15;
                uint32_t d = st + SST_B_HI + (uint32_t)(kr * 304 + ncc * 16);
                size_t so = (size_t)(kof + kr) * N + bn + ncc * 8;
                CP16(d, Whi + so);
                CP16(d + 9728u, Wlo + so);
            }
        }
        CP_COMMIT();
    };

    issue(0, 0);

    for (int c = 0; c < nc; c++) {
        asm volatile("cp.async.wait_group 0;" ::: "memory");
        __syncthreads();
        issue(c + 1, (c + 1) & 1);
        const uint32_t sb = smb + (uint32_t)(c & 1) * SSTAGE;
#pragma unroll
        for (int ks = 0; ks < 2; ks++) {
            uint32_t ah[2][4], al[2][4];
#pragma unroll
            for (int tm = 0; tm < 2; tm++) {
                uint32_t off = aLd + (uint32_t)(tm * 16 * 80 + ks * 32);
                ldsm_x4(ah[tm], sb + off);
                ldsm_x4(al[tm], sb + SST_A_LO + off);
            }
            uint32_t bh[2][4], bl[2][4];
            {
                uint32_t off = bLd + (uint32_t)(ks * 16 * 304);
                ldsm_x4t(bh[0], sb + SST_B_HI + off);
                ldsm_x4t(bl[0], sb + SST_B_LO + off);
            }
#pragma unroll
            for (int p = 0; p < 4; p++) {
                const int cur = p & 1, nxt = cur ^ 1;
                if (p < 3) {
                    uint32_t off = bLd + (uint32_t)(ks * 16 * 304 + (p + 1) * 32);
                    ldsm_x4t(bh[nxt], sb + SST_B_HI + off);
                    ldsm_x4t(bl[nxt], sb + SST_B_LO + off);
                }
#pragma unroll
                for (int h = 0; h < 2; h++) {
#pragma unroll
                    for (int tm = 0; tm < 2; tm++) {
                        mma_bf16(acc[tm][p * 2 + h], ah[tm], bh[cur] + 2 * h);
                        mma_bf16(acc[tm][p * 2 + h], ah[tm], bl[cur] + 2 * h);
                        mma_bf16(acc[tm][p * 2 + h], al[tm], bh[cur] + 2 * h);
                    }
                }
            }
        }
    }

#pragma unroll
    for (int tm = 0; tm < 2; tm++) {
#pragma unroll
        for (int bt = 0; bt < 8; bt++) {
            int r0  = bm + wm * 32 + tm * 16 + (lane >> 2);
            int col = bn + wn * 64 + bt * 8 + (lane & 3) * 2;
            float2 v0 = make_float2(acc[tm][bt][0], acc[tm][bt][1]);
            float2 v1 = make_float2(acc[tm][bt][2], acc[tm][bt][3]);
            if (b0) {
                const float* bp; int cc;
                if (col < 2048)      { bp = b0; cc = col; }
                else if (col < 2560) { bp = b1; cc = col - 2048; }
                else                 { bp = b2; cc = col - 2560; }
                float2 bb = *(const float2*)(bp + cc);
                v0.x += bb.x; v0.y += bb.y;
                v1.x += bb.x; v1.y += bb.y;
            }
            if (res) {
                float2 r0v = *(const float2*)(res + (size_t)r0 * N + col);
                float2 r1v = *(const float2*)(res + (size_t)(r0 + 8) * N + col);
                v0.x += r0v.x; v0.y += r0v.y;
                v1.x += r1v.x; v1.y += r1v.y;
            }
            *(float2*)(C + (size_t)r0 * N + col) = v0;
            *(float2*)(C + (size_t)(r0 + 8) * N + col) = v1;
        }
    }
}

// ======================= BM=256 big GEMM (+ optional 32-col silu epilogue) =======================
#define BST_A_LO 20480u
#define BST_B_HI 40960u
#define BST_B_LO 50688u
#define BSTAGE   60416u
#define BIG_SMEM (3 * 60416)

__global__ __launch_bounds__(512, 1)
void gemm_big_kernel(const __nv_bfloat16* __restrict__ Ahi,
                     const __nv_bfloat16* __restrict__ Alo,
                     const __nv_bfloat16* __restrict__ Whi,
                     const __nv_bfloat16* __restrict__ Wlo,
                     const float* __restrict__ bias, const float* __restrict__ res,
                     float* __restrict__ C,
                     __nv_bfloat16* __restrict__ shi,
                     __nv_bfloat16* __restrict__ slo,
                     int M, int N, int K) {
    extern __shared__ char sm[];
    const uint32_t smb = smem_u32(sm);
    const int tid  = threadIdx.x;
    const int lane = tid & 31;
    const int warp = tid >> 5;
    const int wm = warp & 7;
    const int wn = warp >> 3;
    const int bm = blockIdx.y * 256;
    const int bn = blockIdx.x * 128;

    const uint32_t aLd = (uint32_t)((wm * 32 + (lane & 15)) * 80 +
                                    ((lane >> 4) & 1) * 16);
    const uint32_t bLd = (uint32_t)((lane & 15) * 304 + (lane >> 4) * 16 +
                                    wn * 128);

    float acc[2][8][4];
#pragma unroll
    for (int i = 0; i < 2; i++)
#pragma unroll
        for (int j = 0; j < 8; j++)
#pragma unroll
            for (int q = 0; q < 4; q++) acc[i][j][q] = 0.f;

    const int nc = K >> 5;

    auto issue = [&](int c, int stg) {
        if (c < nc) {
            const uint32_t st = smb + (uint32_t)stg * BSTAGE;
            const size_t kof = (size_t)c * 32;
#pragma unroll
            for (int i = 0; i < 2; i++) {
                int id = tid + i * 512;
                int r = id >> 2, cc = id & 3;
                uint32_t d = st + (uint32_t)(r * 80 + cc * 16);
                size_t so = (size_t)(bm + r) * K + kof + cc * 8;
                CP16(d, Ahi + so);
                CP16(d + BST_A_LO, Alo + so);
            }
            {
                int kr = tid >> 4, ncc = tid & 15;
                uint32_t d = st + BST_B_HI + (uint32_t)(kr * 304 + ncc * 16);
                size_t so = (size_t)(kof + kr) * N + bn + ncc * 8;
                CP16(d, Whi + so);
                CP16(d + 9728u, Wlo + so);
            }
        }
        CP_COMMIT();
    };

    issue(0, 0);
    issue(1, 1);

    for (int c = 0; c < nc; c++) {
        asm volatile("cp.async.wait_group 1;" ::: "memory");
        __syncthreads();
        issue(c + 2, (c + 2) % 3);
        const uint32_t sb = smb + (uint32_t)(c % 3) * BSTAGE;
#pragma unroll
        for (int ks = 0; ks < 2; ks++) {
            uint32_t ah[2][4], al[2][4];
#pragma unroll
            for (int tm = 0; tm < 2; tm++) {
                uint32_t off = aLd + (uint32_t)(tm * 16 * 80 + ks * 32);
                ldsm_x4(ah[tm], sb + off);
                ldsm_x4(al[tm], sb + BST_A_LO + off);
            }
            uint32_t bh[2][4], bl[2][4];
            {
                uint32_t off = bLd + (uint32_t)(ks * 16 * 304);
                ldsm_x4t(bh[0], sb + BST_B_HI + off);
                ldsm_x4t(bl[0], sb + BST_B_LO + off);
            }
#pragma unroll
            for (int p = 0; p < 4; p++) {
                const int cur = p & 1, nxt = cur ^ 1;
                if (p < 3) {
                    uint32_t off = bLd + (uint32_t)(ks * 16 * 304 + (p + 1) * 32);
                    ldsm_x4t(bh[nxt], sb + BST_B_HI + off);
                    ldsm_x4t(bl[nxt], sb + BST_B_LO + off);
                }
#pragma unroll
                for (int h = 0; h < 2; h++) {
#pragma unroll
                    for (int tm = 0; tm < 2; tm++) {
                        mma_bf16(acc[tm][p * 2 + h], ah[tm], bh[cur] + 2 * h);
                        mma_bf16(acc[tm][p * 2 + h], ah[tm], bl[cur] + 2 * h);
                        mma_bf16(acc[tm][p * 2 + h], al[tm], bh[cur] + 2 * h);
                    }
                }
            }
        }
    }

    if (shi) {
        // 32-col interleave: warp's 64 phys cols = 32 gate (bt 0-3) + 32 up (bt 4-7)
        const int NL = N >> 1;
        const int colB = (bn + wn * 64) >> 1;
#pragma unroll
        for (int tm = 0; tm < 2; tm++) {
#pragma unroll
            for (int t = 0; t < 4; t++) {
                int r0   = bm + wm * 32 + tm * 16 + (lane >> 2);
                int colL = colB + t * 8 + (lane & 3) * 2;
                float* gt = acc[tm][t];
                float* up = acc[tm][t + 4];
                float o0 = silu_f(gt[0]) * up[0];
                float o1 = silu_f(gt[1]) * up[1];
                float o2 = silu_f(gt[2]) * up[2];
                float o3 = silu_f(gt[3]) * up[3];
                uint32_t hA, lA, hB, lB;
                hA = splitpack(o0, o1, lA);
                hB = splitpack(o2, o3, lB);
                size_t iA = ((size_t)r0 * NL + colL) >> 1;
                size_t iB = ((size_t)(r0 + 8) * NL + colL) >> 1;
                ((uint32_t*)shi)[iA] = hA;
                ((uint32_t*)slo)[iA] = lA;
                ((uint32_t*)shi)[iB] = hB;
                ((uint32_t*)slo)[iB] = lB;
            }
        }
        return;
    }

#pragma unroll
    for (int tm = 0; tm < 2; tm++) {
#pragma unroll
        for (int bt = 0; bt < 8; bt++) {
            int r0  = bm + wm * 32 + tm * 16 + (lane >> 2);
            int col = bn + wn * 64 + bt * 8 + (lane & 3) * 2;
            float2 v0 = make_float2(acc[tm][bt][0], acc[tm][bt][1]);
            float2 v1 = make_float2(acc[tm][bt][2], acc[tm][bt][3]);
            if (bias) {
                float2 bb = *(const float2*)(bias + col);
                v0.x += bb.x; v0.y += bb.y;
                v1.x += bb.x; v1.y += bb.y;
            }
            if (res) {
                float2 r0v = *(const float2*)(res + (size_t)r0 * N + col);
                float2 r1v = *(const float2*)(res + (size_t)(r0 + 8) * N + col);
                v0.x += r0v.x; v0.y += r0v.y;
                v1.x += r1v.x; v1.y += r1v.y;
            }
            *(float2*)(C + (size_t)r0 * N + col) = v0;
            *(float2*)(C + (size_t)(r0 + 8) * N + col) = v1;
        }
    }
}

// ---------------- RMSNorm -> bf16 hi/lo planes (optional embed gather) ----------------
__global__ void rmsnorm_split_kernel(const float* __restrict__ x,
                                     const int* __restrict__ ids,
                                     const float* __restrict__ emb,
                                     const float* __restrict__ w,
                                     float* __restrict__ hout,
                                     __nv_bfloat16* __restrict__ hi,
                                     __nv_bfloat16* __restrict__ lo) {
    int row = blockIdx.x;
    const float4* xr;
    if (ids) {
        int tok = ids[row];
        xr = (const float4*)(emb + (size_t)tok * HID);
    } else {
        xr = (const float4*)(x + (size_t)row * HID);
    }
    const float4* wr = (const float4*)w;

    float4 v0 = xr[threadIdx.x];
    float4 v1 = xr[threadIdx.x + 256];
    if (hout) {
        ((float4*)(hout + (size_t)row * HID))[threadIdx.x] = v0;
        ((float4*)(hout + (size_t)row * HID))[threadIdx.x + 256] = v1;
    }
    float ss = v0.x * v0.x + v0.y * v0.y + v0.z * v0.z + v0.w * v0.w
             + v1.x * v1.x + v1.y * v1.y + v1.z * v1.z + v1.w * v1.w;

    __shared__ float red[8];
    for (int o = 16; o > 0; o >>= 1) ss += __shfl_down_sync(0xffffffffu, ss, o);
    if ((threadIdx.x & 31) == 0) red[threadIdx.x >> 5] = ss;
    __syncthreads();
    if (threadIdx.x < 8) {
        float t = red[threadIdx.x];
        for (int o = 4; o > 0; o >>= 1) t += __shfl_down_sync(0xffu, t, o);
        if (threadIdx.x == 0) red[0] = t;
    }
    __syncthreads();
    float inv = rsqrtf(red[0] / (float)HID + 1e-6f);

    float4 w0 = wr[threadIdx.x];
    float4 w1 = wr[threadIdx.x + 256];
    float4 o0, o1;
    o0.x = v0.x * inv * w0.x; o0.y = v0.y * inv * w0.y;
    o0.z = v0.z * inv * w0.z; o0.w = v0.w * inv * w0.w;
    o1.x = v1.x * inv * w1.x; o1.y = v1.y * inv * w1.y;
    o1.z = v1.z * inv * w1.z; o1.w = v1.w * inv * w1.w;
    uint2 h, l;
    size_t b = (size_t)row * (HID / 4);
    split4(o0, h, l);
    ((uint2*)hi)[b + threadIdx.x] = h;
    ((uint2*)lo)[b + threadIdx.x] = l;
    split4(o1, h, l);
    ((uint2*)hi)[b + threadIdx.x + 256] = h;
    ((uint2*)lo)[b + threadIdx.x + 256] = l;
}

// ---------------- RoPE: fp32 qkv -> rotated bf16 hi/lo planes ----------------
__global__ void rope_split_kernel(const float* __restrict__ qkv,
                                  __nv_bfloat16* __restrict__ hi,
                                  __nv_bfloat16* __restrict__ lo) {
    int s = blockIdx.x;
    int hh = blockIdx.y;
    int i = threadIdx.x;
    size_t base = (size_t)s * NQKV +
        ((hh < NHEAD) ? hh * HDIM
         : (hh < NHEAD + NKVH) ? HID + (hh - NHEAD) * HDIM
         : HID + NKVH * HDIM + (hh - NHEAD - NKVH) * HDIM);
    float x1 = qkv[base + i];
    float x2 = qkv[base + i + 64];
    float y1, y2;
    if (hh < NHEAD + NKVH) {
        float inv = powf(1000000.0f, -(float)i / 64.0f);
        float f = (float)s * inv;
        float c = cosf(f), sn = sinf(f);
        y1 = x1 * c - x2 * sn;
        y2 = x2 * c + x1 * sn;
    } else {
        y1 = x1; y2 = x2;
    }
    uint16_t h1, l1, h2, l2;
    split1(y1, h1, l1);
    split1(y2, h2, l2);
    ((uint16_t*)hi)[base + i]      = h1;
    ((uint16_t*)lo)[base + i]      = l1;
    ((uint16_t*)hi)[base + i + 64] = h2;
    ((uint16_t*)lo)[base + i + 64] = l2;
}

// ---------------- tensor-core flash attention (bf16x3, causal, GQA) ----------------
#define ATT_STRIDE 136
#define ATT_PLANE  (64 * ATT_STRIDE * 2)
#define ATT_SMEM   (6 * ATT_PLANE)

__global__ __launch_bounds__(128) void attn_mma_kernel(
    const __nv_bfloat16* __restrict__ qhi, const __nv_bfloat16* __restrict__ qlo,
    __nv_bfloat16* __restrict__ ohi, __nv_bfloat16* __restrict__ olo) {
    extern __shared__ char smc[];
    const uint32_t smb = smem_u32(smc);
    const uint32_t Qh = smb,            Ql = Qh + ATT_PLANE;
    const uint32_t Kh = Ql + ATT_PLANE, Kl = Kh + ATT_PLANE;
    const uint32_t Vh = Kl + ATT_PLANE, Vl = Vh + ATT_PLANE;

    const int head = blockIdx.x;
    const int qb   = blockIdx.y;
    const int kvh  = head >> 2;
    const int tid  = threadIdx.x;
    const int lane = tid & 31;
    const int warp = tid >> 5;

#pragma unroll
    for (int i = 0; i < 8; i++) {
        int id = tid + i * 128;
        int r = id >> 4, c = id & 15;
        uint32_t d = (uint32_t)(r * ATT_STRIDE * 2 + c * 16);
        size_t so = (size_t)(qb * 64 + r) * NQKV + head * HDIM + c * 8;
        CP16(Qh + d, qhi + so);
        CP16(Ql + d, qlo + so);
    }
    CP_COMMIT();

    float o[16][4];
#pragma unroll
    for (int t = 0; t < 16; t++)
#pragma unroll
        for (int q = 0; q < 4; q++) o[t][q] = 0.f;
    float mA = -1e30f, mB = -1e30f, lA = 0.f, lB = 0.f;

    const uint32_t qLd = (uint32_t)((warp * 16 + (lane & 15)) * ATT_STRIDE * 2 +
                                    ((lane >> 4) & 1) * 16);
    const uint32_t kLd = (uint32_t)((lane & 7) * ATT_STRIDE * 2 +
                                    ((lane >> 3) & 1) * 16);
    const uint32_t vLd = (uint32_t)((lane & 15) * ATT_STRIDE * 2 +
                                    ((lane >> 4) & 1) * 16);
    const float scale = 0.08838834764831845f;
    const int rowA = warp * 16 + (lane >> 2);
    const int rowB = rowA + 8;

    for (int kb = 0; kb <= qb; kb++) {
        __syncthreads();
#pragma unroll
        for (int i = 0; i < 8; i++) {
            int id = tid + i * 128;
            int r = id >> 4, c = id & 15;
            uint32_t d = (uint32_t)(r * ATT_STRIDE * 2 + c * 16);
            size_t ko = (size_t)(kb * 64 + r) * NQKV + HID + kvh * HDIM + c * 8;
            size_t vo = ko + NKVH * HDIM;
            CP16(Kh + d, qhi + ko);
            CP16(Kl + d, qlo + ko);
            CP16(Vh + d, qhi + vo);
            CP16(Vl + d, qlo + vo);
        }
        CP_COMMIT();
        asm volatile("cp.async.wait_group 0;" ::: "memory");
        __syncthreads();

        float s[8][4];
#pragma unroll
        for (int t = 0; t < 8; t++)
#pragma unroll
            for (int q = 0; q < 4; q++) s[t][q] = 0.f;
#pragma unroll
        for (int ds = 0; ds < 8; ds++) {
            uint32_t ah[4], al[4];
            ldsm_x4(ah, Qh + qLd + ds * 32);
            ldsm_x4(al, Ql + qLd + ds * 32);
#pragma unroll
            for (int nt = 0; nt < 8; nt++) {
                uint32_t ko = kLd + (uint32_t)(nt * 8 * ATT_STRIDE * 2 + ds * 32);
                uint32_t bh[2], bl[2];
                ldsm_x2(bh, Kh + ko);
                ldsm_x2(bl, Kl + ko);
                mma_bf16(s[nt], ah, bh);
                mma_bf16(s[nt], ah, bl);
                mma_bf16(s[nt], al, bh);
            }
        }

#pragma unroll
        for (int nt = 0; nt < 8; nt++) {
#pragma unroll
            for (int q = 0; q < 4; q++) s[nt][q] *= scale;
            if (kb == qb) {
                int c0 = nt * 8 + (lane & 3) * 2;
                if (c0 > rowA)     s[nt][0] = -1e9f;
                if (c0 + 1 > rowA) s[nt][1] = -1e9f;
                if (c0 > rowB)     s[nt][2] = -1e9f;
                if (c0 + 1 > rowB) s[nt][3] = -1e9f;
            }
        }

        float mxA = -1e30f, mxB = -1e30f;
#pragma unroll
        for (int nt = 0; nt < 8; nt++) {
            mxA = fmaxf(mxA, fmaxf(s[nt][0], s[nt][1]));
            mxB = fmaxf(mxB, fmaxf(s[nt][2], s[nt][3]));
        }
        mxA = fmaxf(mxA, __shfl_xor_sync(0xffffffffu, mxA, 1));
        mxA = fmaxf(mxA, __shfl_xor_sync(0xffffffffu, mxA, 2));
        mxB = fmaxf(mxB, __shfl_xor_sync(0xffffffffu, mxB, 1));
        mxB = fmaxf(mxB, __shfl_xor_sync(0xffffffffu, mxB, 2));
        float mAn = fmaxf(mA, mxA), mBn = fmaxf(mB, mxB);
        float aAf = expf(mA - mAn), aBf = expf(mB - mBn);
        float pA = 0.f, pB = 0.f;
#pragma unroll
        for (int nt = 0; nt < 8; nt++) {
            s[nt][0] = expf(s[nt][0] - mAn);
            s[nt][1] = expf(s[nt][1] - mAn);
            s[nt][2] = expf(s[nt][2] - mBn);
            s[nt][3] = expf(s[nt][3] - mBn);
            pA += s[nt][0] + s[nt][1];
            pB += s[nt][2] + s[nt][3];
        }
        pA += __shfl_xor_sync(0xffffffffu, pA, 1);
        pA += __shfl_xor_sync(0xffffffffu, pA, 2);
        pB += __shfl_xor_sync(0xffffffffu, pB, 1);
        pB += __shfl_xor_sync(0xffffffffu, pB, 2);
        lA = lA * aAf + pA;
        lB = lB * aBf + pB;
        mA = mAn;
        mB = mBn;
#pragma unroll
        for (int t = 0; t < 16; t++) {
            o[t][0] *= aAf; o[t][1] *= aAf;
            o[t][2] *= aBf; o[t][3] *= aBf;
        }

#pragma unroll
        for (int ks = 0; ks < 4; ks++) {
            uint32_t ph[4], pl[4];
            ph[0] = splitpack(s[2 * ks][0],     s[2 * ks][1],     pl[0]);
            ph[1] = splitpack(s[2 * ks][2],     s[2 * ks][3],     pl[1]);
            ph[2] = splitpack(s[2 * ks + 1][0], s[2 * ks + 1][1], pl[2]);
            ph[3] = splitpack(s[2 * ks + 1][2], s[2 * ks + 1][3], pl[3]);
#pragma unroll
            for (int dt = 0; dt < 8; dt++) {
                uint32_t vo = vLd + (uint32_t)(ks * 16 * ATT_STRIDE * 2 + dt * 32);
                uint32_t vh[4], vl[4];
                ldsm_x4t(vh, Vh + vo);
                ldsm_x4t(vl, Vl + vo);
#pragma unroll
                for (int h = 0; h < 2; h++) {
                    float* od = o[dt * 2 + h];
                    mma_bf16(od, ph, vh + 2 * h);
                    mma_bf16(od, ph, vl + 2 * h);
                    mma_bf16(od, pl, vh + 2 * h);
                }
            }
        }
    }

    float liA = 1.0f / lA, liB = 1.0f / lB;
    int gRowA = qb * 64 + rowA;
    int gRowB = qb * 64 + rowB;
#pragma unroll
    for (int nt = 0; nt < 16; nt++) {
        int col = head * HDIM + nt * 8 + (lane & 3) * 2;
        uint32_t hA, lAo, hB, lBo;
        hA = splitpack(o[nt][0] * liA, o[nt][1] * liA, lAo);
        hB = splitpack(o[nt][2] * liB, o[nt][3] * liB, lBo);
        size_t iA = ((size_t)gRowA * HID + col) >> 1;
        size_t iB = ((size_t)gRowB * HID + col) >> 1;
        ((uint32_t*)ohi)[iA] = hA;
        ((uint32_t*)olo)[iA] = lAo;
        ((uint32_t*)ohi)[iB] = hB;
        ((uint32_t*)olo)[iB] = lBo;
    }
}

// ---------------- host orchestration ----------------
static __nv_bfloat16 *s_ahi, *s_alo, *s_fhi, *s_flo, *s_whi, *s_wlo,
                     *s_qhi, *s_qlo;

static void run_split(const float* src, size_t n) {
    int nT = (int)(n / 16);
    split_kernel<<<nT / 256, 256>>>(src, s_whi, s_wlo, nT);
}

extern "C" void kernel_launch(void* const* d_in, const int* in_sizes, int n_in,
                              void* d_out, int out_size) {
    const int*   ids    = (const int*)d_in[0];
    const float* emb    = (const float*)d_in[1];
    const float* Wq     = (const float*)d_in[2];
    const float* bq     = (const float*)d_in[3];
    const float* Wk     = (const float*)d_in[4];
    const float* bk     = (const float*)d_in[5];
    const float* Wv     = (const float*)d_in[6];
    const float* bv     = (const float*)d_in[7];
    const float* Wo     = (const float*)d_in[8];
    const float* ln1    = (const float*)d_in[9];
    const float* ln2    = (const float*)d_in[10];
    const float* Wg     = (const float*)d_in[11];
    const float* Wu     = (const float*)d_in[12];
    const float* Wd     = (const float*)d_in[13];
    const float* norm_w = (const float*)d_in[14];
    const float* Wlm    = (const float*)d_in[15];
    const float* blm    = (const float*)d_in[16];
    float* out = (float*)d_out;

    float* base = nullptr;
    cudaGetSymbolAddress((void**)&base, g_scratch);
    cudaGetSymbolAddress((void**)&s_ahi, g_ahi);
    cudaGetSymbolAddress((void**)&s_alo, g_alo);
    cudaGetSymbolAddress((void**)&s_fhi, g_fhi);
    cudaGetSymbolAddress((void**)&s_flo, g_flo);
    cudaGetSymbolAddress((void**)&s_whi, g_whi);
    cudaGetSymbolAddress((void**)&s_wlo, g_wlo);
    cudaGetSymbolAddress((void**)&s_qhi, g_qkvhi);
    cudaGetSymbolAddress((void**)&s_qlo, g_qkvlo);

    float* hbuf  = base;
    float* qkv   = base + (size_t)SH;

    cudaFuncSetAttribute(attn_mma_kernel,
                         cudaFuncAttributeMaxDynamicSharedMemorySize, ATT_SMEM);
    cudaFuncSetAttribute(gemm_sml_kernel,
                         cudaFuncAttributeMaxDynamicSharedMemorySize, SML_SMEM);
    cudaFuncSetAttribute(gemm_big_kernel,
                         cudaFuncAttributeMaxDynamicSharedMemorySize, BIG_SMEM);

    for (int l = 0; l < NLAYER; l++) {
        const float* Wql = Wq + (size_t)l * HID * HID;
        const float* bql = bq + (size_t)l * HID;
        const float* Wkl = Wk + (size_t)l * HID * (NKVH * HDIM);
        const float* bkl = bk + (size_t)l * (NKVH * HDIM);
        const float* Wvl = Wv + (size_t)l * HID * (NKVH * HDIM);
        const float* bvl = bv + (size_t)l * (NKVH * HDIM);
        const float* Wol = Wo + (size_t)l * HID * HID;
        const float* l1  = ln1 + (size_t)l * HID;
        const float* l2  = ln2 + (size_t)l * HID;
        const float* Wgl = Wg + (size_t)l * HID * FFD;
        const float* Wul = Wu + (size_t)l * HID * FFD;
        const float* Wdl = Wd + (size_t)l * FFD * HID;

        // ---- fused QKV projection ----
        {
            int nT = (int)((size_t)HID * HID / 16);
            split2d_kernel<<<nT / 256, 256>>>(
                Wql, s_whi, s_wlo, HID / 8, NQKV / 8, nT);
        }
        {
            int nT = HID * 1024 / 16;
            splitkv_kernel<<<nT / 256, 256>>>(Wkl, Wvl, s_whi, s_wlo, nT);
        }
        if (l == 0)
            rmsnorm_split_kernel<<<SQ, 256>>>(nullptr, ids, emb, l1, hbuf,
                                              s_ahi, s_alo);
        else
            rmsnorm_split_kernel<<<SQ, 256>>>(hbuf, nullptr, nullptr, l1,
                                              nullptr, s_ahi, s_alo);
        {
            dim3 grid(NQKV / 128, SQ / 128);
            gemm_sml_kernel<<<grid, 256, SML_SMEM>>>(
                s_ahi, s_alo, s_whi, s_wlo, bql, bkl, bvl, nullptr, qkv,
                SQ, NQKV, HID);
        }

        // ---- RoPE + split ----
        dim3 rgrid(SQ, NHEAD + 2 * NKVH);
        rope_split_kernel<<<rgrid, 64>>>(qkv, s_qhi, s_qlo);

        // ---- attention -> activation planes ----
        dim3 agrid(NHEAD, SQ / 64);
        attn_mma_kernel<<<agrid, 128, ATT_SMEM>>>(s_qhi, s_qlo, s_ahi, s_alo);

        // ---- O projection (+residual) ----
        run_split(Wol, (size_t)HID * HID);
        {
            dim3 grid(HID / 128, SQ / 128);
            gemm_sml_kernel<<<grid, 256, SML_SMEM>>>(
                s_ahi, s_alo, s_whi, s_wlo, nullptr, nullptr, nullptr, hbuf,
                hbuf, SQ, HID, HID);
        }

        // ---- FF: fused gate|up (32-col interleave) with silu epilogue ----
        rmsnorm_split_kernel<<<SQ, 256>>>(hbuf, nullptr, nullptr, l2,
                                          nullptr, s_ahi, s_alo);
        {
            int nT = (int)((size_t)HID * NFF2 / 16);   // 2M threads
            splitgu_kernel<<<nT / 256, 256>>>(Wgl, Wul, s_whi, s_wlo, nT);
        }
        {
            dim3 grid(NFF2 / 128, SQ / 256);
            gemm_big_kernel<<<grid, 512, BIG_SMEM>>>(
                s_ahi, s_alo, s_whi, s_wlo, nullptr, nullptr, nullptr,
                s_fhi, s_flo, SQ, NFF2, HID);
        }
        // ---- down projection (+residual) ----
        run_split(Wdl, (size_t)FFD * HID);
        {
            dim3 grid(HID / 128, SQ / 256);
            gemm_big_kernel<<<grid, 512, BIG_SMEM>>>(
                s_fhi, s_flo, s_whi, s_wlo, nullptr, hbuf, hbuf,
                nullptr, nullptr, SQ, HID, FFD);
        }
    }

    rmsnorm_split_kernel<<<SQ, 256>>>(hbuf, nullptr, nullptr, norm_w,
                                      nullptr, s_ahi, s_alo);
    run_split(Wlm, (size_t)HID * VOC);
    {
        dim3 grid(VOC / 128, SQ / 256);
        gemm_big_kernel<<<grid, 512, BIG_SMEM>>>(
            s_ahi, s_alo, s_whi, s_wlo, blm, nullptr, out,
            nullptr, nullptr, SQ, VOC, HID);
    }
}

// round 15
// speedup vs baseline: 1.0613x; 1.0375x over previous
#include <cuda_runtime.h>
#include <cuda_bf16.h>
#include <math.h>
#include <cstdint>

// ---------------- problem constants ----------------
#define SQ     2048
#define HID    2048
#define VOC    32000
#define NHEAD  16
#define NKVH   4
#define HDIM   128
#define FFD    8192
#define NLAYER 4
#define NQKV   3072   // 2048 + 512 + 512
#define NFF2   16384  // fused gate|up (contiguous halves)

#define SH  (SQ * HID)
#define SFF (SQ * FFD)

__device__ float g_scratch[(size_t)SH + (size_t)SQ * NQKV + 2 * (size_t)SFF];
__device__ __nv_bfloat16 g_ahi[(size_t)SFF];
__device__ __nv_bfloat16 g_alo[(size_t)SFF];
__device__ __nv_bfloat16 g_whi[(size_t)HID * VOC];
__device__ __nv_bfloat16 g_wlo[(size_t)HID * VOC];
__device__ __nv_bfloat16 g_qkvhi[(size_t)SQ * NQKV];
__device__ __nv_bfloat16 g_qkvlo[(size_t)SQ * NQKV];
__device__ float g_rope[SQ * 64 * 2];   // cos|sin per (pos, freq)

// ======================= helpers =======================
__device__ __forceinline__ uint32_t smem_u32(const void* p) {
    uint32_t a;
    asm("{ .reg .u64 t; cvta.to.shared.u64 t, %1; cvt.u32.u64 %0, t; }"
        : "=r"(a) : "l"(p));
    return a;
}
__device__ __forceinline__ void ldsm_x4(uint32_t* r, uint32_t addr) {
    asm volatile("ldmatrix.sync.aligned.m8n8.x4.shared.b16 {%0,%1,%2,%3}, [%4];"
                 : "=r"(r[0]), "=r"(r[1]), "=r"(r[2]), "=r"(r[3]) : "r"(addr));
}
__device__ __forceinline__ void ldsm_x2(uint32_t* r, uint32_t addr) {
    asm volatile("ldmatrix.sync.aligned.m8n8.x2.shared.b16 {%0,%1}, [%2];"
                 : "=r"(r[0]), "=r"(r[1]) : "r"(addr));
}
__device__ __forceinline__ void ldsm_x4t(uint32_t* r, uint32_t addr) {
    asm volatile("ldmatrix.sync.aligned.m8n8.x4.trans.shared.b16 {%0,%1,%2,%3}, [%4];"
                 : "=r"(r[0]), "=r"(r[1]), "=r"(r[2]), "=r"(r[3]) : "r"(addr));
}
__device__ __forceinline__ void mma_bf16(float* c, const uint32_t* a,
                                         const uint32_t* b) {
    asm volatile("mma.sync.aligned.m16n8k16.row.col.f32.bf16.bf16.f32 "
                 "{%0,%1,%2,%3}, {%4,%5,%6,%7}, {%8,%9}, {%0,%1,%2,%3};"
                 : "+f"(c[0]), "+f"(c[1]), "+f"(c[2]), "+f"(c[3])
                 : "r"(a[0]), "r"(a[1]), "r"(a[2]), "r"(a[3]),
                   "r"(b[0]), "r"(b[1]));
}
__device__ __forceinline__ uint32_t pack2(__nv_bfloat16 a, __nv_bfloat16 b) {
    uint16_t ua = *(uint16_t*)&a, ub = *(uint16_t*)&b;
    return ((uint32_t)ub << 16) | (uint32_t)ua;
}
__device__ __forceinline__ void split4(float4 f, uint2& hi, uint2& lo) {
    __nv_bfloat16 hx = __float2bfloat16_rn(f.x);
    __nv_bfloat16 hy = __float2bfloat16_rn(f.y);
    __nv_bfloat16 hz = __float2bfloat16_rn(f.z);
    __nv_bfloat16 hw = __float2bfloat16_rn(f.w);
    __nv_bfloat16 lx = __float2bfloat16_rn(f.x - __bfloat162float(hx));
    __nv_bfloat16 ly = __float2bfloat16_rn(f.y - __bfloat162float(hy));
    __nv_bfloat16 lz = __float2bfloat16_rn(f.z - __bfloat162float(hz));
    __nv_bfloat16 lw = __float2bfloat16_rn(f.w - __bfloat162float(hw));
    hi = make_uint2(pack2(hx, hy), pack2(hz, hw));
    lo = make_uint2(pack2(lx, ly), pack2(lz, lw));
}
__device__ __forceinline__ void split1(float x, uint16_t& h, uint16_t& l) {
    __nv_bfloat16 hb = __float2bfloat16_rn(x);
    __nv_bfloat16 lb = __float2bfloat16_rn(x - __bfloat162float(hb));
    h = *(uint16_t*)&hb;
    l = *(uint16_t*)&lb;
}
__device__ __forceinline__ uint32_t splitpack(float a, float b, uint32_t& lo) {
    uint16_t ha, la, hb, lb;
    split1(a, ha, la);
    split1(b, hb, lb);
    lo = ((uint32_t)lb << 16) | la;
    return ((uint32_t)hb << 16) | ha;
}
#define CP16(dst, src) \
    asm volatile("cp.async.cg.shared.global [%0], [%1], 16;" :: "r"(dst), "l"(src))
#define CP_COMMIT() asm volatile("cp.async.commit_group;" ::: "memory")

// ---------------- weight splits ----------------
__global__ void split_kernel(const float* __restrict__ src,
                             __nv_bfloat16* __restrict__ hi,
                             __nv_bfloat16* __restrict__ lo, int nT) {
    int i = blockIdx.x * blockDim.x + threadIdx.x;
    float4 f[4];
#pragma unroll
    for (int j = 0; j < 4; j++) f[j] = ((const float4*)src)[4 * i + j];
    uint2 h[4], l[4];
#pragma unroll
    for (int j = 0; j < 4; j++) split4(f[j], h[j], l[j]);
    ((uint4*)hi)[2 * i]     = make_uint4(h[0].x, h[0].y, h[1].x, h[1].y);
    ((uint4*)hi)[2 * i + 1] = make_uint4(h[2].x, h[2].y, h[3].x, h[3].y);
    ((uint4*)lo)[2 * i]     = make_uint4(l[0].x, l[0].y, l[1].x, l[1].y);
    ((uint4*)lo)[2 * i + 1] = make_uint4(l[2].x, l[2].y, l[3].x, l[3].y);
}
__global__ void split2d_kernel(const float* __restrict__ src,
                               __nv_bfloat16* __restrict__ hi,
                               __nv_bfloat16* __restrict__ lo,
                               int n8row, int ld8, int nT) {
    int i = blockIdx.x * blockDim.x + threadIdx.x;
    int g = 2 * i;
    int r = g / n8row, c8 = g - r * n8row;
    float4 f[4];
#pragma unroll
    for (int j = 0; j < 4; j++) f[j] = ((const float4*)src)[4 * i + j];
    uint2 h[4], l[4];
#pragma unroll
    for (int j = 0; j < 4; j++) split4(f[j], h[j], l[j]);
    size_t o = (size_t)r * ld8 + c8;
    ((uint4*)hi)[o]     = make_uint4(h[0].x, h[0].y, h[1].x, h[1].y);
    ((uint4*)hi)[o + 1] = make_uint4(h[2].x, h[2].y, h[3].x, h[3].y);
    ((uint4*)lo)[o]     = make_uint4(l[0].x, l[0].y, l[1].x, l[1].y);
    ((uint4*)lo)[o + 1] = make_uint4(l[2].x, l[2].y, l[3].x, l[3].y);
}
__global__ void splitkv_kernel(const float* __restrict__ Wk,
                               const float* __restrict__ Wv,
                               __nv_bfloat16* __restrict__ hi,
                               __nv_bfloat16* __restrict__ lo, int nT) {
    int i = blockIdx.x * blockDim.x + threadIdx.x;
    int g0 = 2 * i;
    int r  = g0 >> 7;
    int c0 = g0 & 127;
#pragma unroll
    for (int t = 0; t < 2; t++) {
        int c = c0 + t;
        const float* s = (c < 64) ? Wk + (size_t)r * 512 + c * 8
                                  : Wv + (size_t)r * 512 + (c - 64) * 8;
        float4 f0 = ((const float4*)s)[0];
        float4 f1 = ((const float4*)s)[1];
        uint2 h0, l0, h1, l1;
        split4(f0, h0, l0);
        split4(f1, h1, l1);
        size_t o = (size_t)r * (NQKV / 8) + (HID / 8) + c;
        ((uint4*)hi)[o] = make_uint4(h0.x, h0.y, h1.x, h1.y);
        ((uint4*)lo)[o] = make_uint4(l0.x, l0.y, l1.x, l1.y);
    }
}

// ---------------- RoPE LUT (once per forward) ----------------
__global__ void rope_lut_kernel(float* __restrict__ lut) {
    int s = blockIdx.x;
    int i = threadIdx.x;   // 0..63
    float inv = powf(1000000.0f, -(float)i / 64.0f);
    float f = (float)s * inv;
    lut[(s * 64 + i) * 2]     = cosf(f);
    lut[(s * 64 + i) * 2 + 1] = sinf(f);
}

// ======================= BM=128 GEMM (R9-proven) =======================
#define SST_A_LO 10240u
#define SST_B_HI 20480u
#define SST_B_LO 30208u
#define SSTAGE   39936u
#define SML_SMEM (2 * 39936)

__global__ __launch_bounds__(256, 2)
void gemm_sml_kernel(const __nv_bfloat16* __restrict__ Ahi,
                     const __nv_bfloat16* __restrict__ Alo,
                     const __nv_bfloat16* __restrict__ Whi,
                     const __nv_bfloat16* __restrict__ Wlo,
                     const float* __restrict__ b0, const float* __restrict__ b1,
                     const float* __restrict__ b2, const float* __restrict__ res,
                     float* __restrict__ C, int M, int N, int K) {
    extern __shared__ char sm[];
    const uint32_t smb = smem_u32(sm);
    const int tid  = threadIdx.x;
    const int lane = tid & 31;
    const int warp = tid >> 5;
    const int wm = warp & 3;
    const int wn = warp >> 2;
    const int bm = blockIdx.y * 128;
    const int bn = blockIdx.x * 128;

    const uint32_t aLd = (uint32_t)((wm * 32 + (lane & 15)) * 80 +
                                    ((lane >> 4) & 1) * 16);
    const uint32_t bLd = (uint32_t)((lane & 15) * 304 + (lane >> 4) * 16 +
                                    wn * 128);

    float acc[2][8][4];
#pragma unroll
    for (int i = 0; i < 2; i++)
#pragma unroll
        for (int j = 0; j < 8; j++)
#pragma unroll
            for (int q = 0; q < 4; q++) acc[i][j][q] = 0.f;

    const int nc = K >> 5;

    auto issue = [&](int c, int stg) {
        if (c < nc) {
            const uint32_t st = smb + (uint32_t)stg * SSTAGE;
            const size_t kof = (size_t)c * 32;
#pragma unroll
            for (int i = 0; i < 2; i++) {
                int id = tid + i * 256;
                int r = id >> 2, cc = id & 3;
                uint32_t d = st + (uint32_t)(r * 80 + cc * 16);
                size_t so = (size_t)(bm + r) * K + kof + cc * 8;
                CP16(d, Ahi + so);
                CP16(d + SST_A_LO, Alo + so);
            }
#pragma unroll
            for (int i = 0; i < 2; i++) {
                int id = tid + i * 256;
                int kr = id >> 4, ncc = id & 15;
                uint32_t d = st + SST_B_HI + (uint32_t)(kr * 304 + ncc * 16);
                size_t so = (size_t)(kof + kr) * N + bn + ncc * 8;
                CP16(d, Whi + so);
                CP16(d + 9728u, Wlo + so);
            }
        }
        CP_COMMIT();
    };

    issue(0, 0);

    for (int c = 0; c < nc; c++) {
        asm volatile("cp.async.wait_group 0;" ::: "memory");
        __syncthreads();
        issue(c + 1, (c + 1) & 1);
        const uint32_t sb = smb + (uint32_t)(c & 1) * SSTAGE;
#pragma unroll
        for (int ks = 0; ks < 2; ks++) {
            uint32_t ah[2][4], al[2][4];
#pragma unroll
            for (int tm = 0; tm < 2; tm++) {
                uint32_t off = aLd + (uint32_t)(tm * 16 * 80 + ks * 32);
                ldsm_x4(ah[tm], sb + off);
                ldsm_x4(al[tm], sb + SST_A_LO + off);
            }
            uint32_t bh[2][4], bl[2][4];
            {
                uint32_t off = bLd + (uint32_t)(ks * 16 * 304);
                ldsm_x4t(bh[0], sb + SST_B_HI + off);
                ldsm_x4t(bl[0], sb + SST_B_LO + off);
            }
#pragma unroll
            for (int p = 0; p < 4; p++) {
                const int cur = p & 1, nxt = cur ^ 1;
                if (p < 3) {
                    uint32_t off = bLd + (uint32_t)(ks * 16 * 304 + (p + 1) * 32);
                    ldsm_x4t(bh[nxt], sb + SST_B_HI + off);
                    ldsm_x4t(bl[nxt], sb + SST_B_LO + off);
                }
#pragma unroll
                for (int h = 0; h < 2; h++) {
#pragma unroll
                    for (int tm = 0; tm < 2; tm++) {
                        mma_bf16(acc[tm][p * 2 + h], ah[tm], bh[cur] + 2 * h);
                        mma_bf16(acc[tm][p * 2 + h], ah[tm], bl[cur] + 2 * h);
                        mma_bf16(acc[tm][p * 2 + h], al[tm], bh[cur] + 2 * h);
                    }
                }
            }
        }
    }

#pragma unroll
    for (int tm = 0; tm < 2; tm++) {
#pragma unroll
        for (int bt = 0; bt < 8; bt++) {
            int r0  = bm + wm * 32 + tm * 16 + (lane >> 2);
            int col = bn + wn * 64 + bt * 8 + (lane & 3) * 2;
            float2 v0 = make_float2(acc[tm][bt][0], acc[tm][bt][1]);
            float2 v1 = make_float2(acc[tm][bt][2], acc[tm][bt][3]);
            if (b0) {
                const float* bp; int cc;
                if (col < 2048)      { bp = b0; cc = col; }
                else if (col < 2560) { bp = b1; cc = col - 2048; }
                else                 { bp = b2; cc = col - 2560; }
                float2 bb = *(const float2*)(bp + cc);
                v0.x += bb.x; v0.y += bb.y;
                v1.x += bb.x; v1.y += bb.y;
            }
            if (res) {
                float2 r0v = *(const float2*)(res + (size_t)r0 * N + col);
                float2 r1v = *(const float2*)(res + (size_t)(r0 + 8) * N + col);
                v0.x += r0v.x; v0.y += r0v.y;
                v1.x += r1v.x; v1.y += r1v.y;
            }
            *(float2*)(C + (size_t)r0 * N + col) = v0;
            *(float2*)(C + (size_t)(r0 + 8) * N + col) = v1;
        }
    }
}

// ======================= BM=256 big GEMM (R8-proven) =======================
#define BST_A_LO 20480u
#define BST_B_HI 40960u
#define BST_B_LO 50688u
#define BSTAGE   60416u
#define BIG_SMEM (3 * 60416)

__global__ __launch_bounds__(512, 1)
void gemm_big_kernel(const __nv_bfloat16* __restrict__ Ahi,
                     const __nv_bfloat16* __restrict__ Alo,
                     const __nv_bfloat16* __restrict__ Whi,
                     const __nv_bfloat16* __restrict__ Wlo,
                     const float* __restrict__ bias, const float* __restrict__ res,
                     float* __restrict__ C, int M, int N, int K) {
    extern __shared__ char sm[];
    const uint32_t smb = smem_u32(sm);
    const int tid  = threadIdx.x;
    const int lane = tid & 31;
    const int warp = tid >> 5;
    const int wm = warp & 7;
    const int wn = warp >> 3;
    const int bm = blockIdx.y * 256;
    const int bn = blockIdx.x * 128;

    const uint32_t aLd = (uint32_t)((wm * 32 + (lane & 15)) * 80 +
                                    ((lane >> 4) & 1) * 16);
    const uint32_t bLd = (uint32_t)((lane & 15) * 304 + (lane >> 4) * 16 +
                                    wn * 128);

    float acc[2][8][4];
#pragma unroll
    for (int i = 0; i < 2; i++)
#pragma unroll
        for (int j = 0; j < 8; j++)
#pragma unroll
            for (int q = 0; q < 4; q++) acc[i][j][q] = 0.f;

    const int nc = K >> 5;

    auto issue = [&](int c, int stg) {
        if (c < nc) {
            const uint32_t st = smb + (uint32_t)stg * BSTAGE;
            const size_t kof = (size_t)c * 32;
#pragma unroll
            for (int i = 0; i < 2; i++) {
                int id = tid + i * 512;
                int r = id >> 2, cc = id & 3;
                uint32_t d = st + (uint32_t)(r * 80 + cc * 16);
                size_t so = (size_t)(bm + r) * K + kof + cc * 8;
                CP16(d, Ahi + so);
                CP16(d + BST_A_LO, Alo + so);
            }
            {
                int kr = tid >> 4, ncc = tid & 15;
                uint32_t d = st + BST_B_HI + (uint32_t)(kr * 304 + ncc * 16);
                size_t so = (size_t)(kof + kr) * N + bn + ncc * 8;
                CP16(d, Whi + so);
                CP16(d + 9728u, Wlo + so);
            }
        }
        CP_COMMIT();
    };

    issue(0, 0);
    issue(1, 1);

    for (int c = 0; c < nc; c++) {
        asm volatile("cp.async.wait_group 1;" ::: "memory");
        __syncthreads();
        issue(c + 2, (c + 2) % 3);
        const uint32_t sb = smb + (uint32_t)(c % 3) * BSTAGE;
#pragma unroll
        for (int ks = 0; ks < 2; ks++) {
            uint32_t ah[2][4], al[2][4];
#pragma unroll
            for (int tm = 0; tm < 2; tm++) {
                uint32_t off = aLd + (uint32_t)(tm * 16 * 80 + ks * 32);
                ldsm_x4(ah[tm], sb + off);
                ldsm_x4(al[tm], sb + BST_A_LO + off);
            }
            uint32_t bh[2][4], bl[2][4];
            {
                uint32_t off = bLd + (uint32_t)(ks * 16 * 304);
                ldsm_x4t(bh[0], sb + BST_B_HI + off);
                ldsm_x4t(bl[0], sb + BST_B_LO + off);
            }
#pragma unroll
            for (int p = 0; p < 4; p++) {
                const int cur = p & 1, nxt = cur ^ 1;
                if (p < 3) {
                    uint32_t off = bLd + (uint32_t)(ks * 16 * 304 + (p + 1) * 32);
                    ldsm_x4t(bh[nxt], sb + BST_B_HI + off);
                    ldsm_x4t(bl[nxt], sb + BST_B_LO + off);
                }
#pragma unroll
                for (int h = 0; h < 2; h++) {
#pragma unroll
                    for (int tm = 0; tm < 2; tm++) {
                        mma_bf16(acc[tm][p * 2 + h], ah[tm], bh[cur] + 2 * h);
                        mma_bf16(acc[tm][p * 2 + h], ah[tm], bl[cur] + 2 * h);
                        mma_bf16(acc[tm][p * 2 + h], al[tm], bh[cur] + 2 * h);
                    }
                }
            }
        }
    }

#pragma unroll
    for (int tm = 0; tm < 2; tm++) {
#pragma unroll
        for (int bt = 0; bt < 8; bt++) {
            int r0  = bm + wm * 32 + tm * 16 + (lane >> 2);
            int col = bn + wn * 64 + bt * 8 + (lane & 3) * 2;
            float2 v0 = make_float2(acc[tm][bt][0], acc[tm][bt][1]);
            float2 v1 = make_float2(acc[tm][bt][2], acc[tm][bt][3]);
            if (bias) {
                float2 bb = *(const float2*)(bias + col);
                v0.x += bb.x; v0.y += bb.y;
                v1.x += bb.x; v1.y += bb.y;
            }
            if (res) {
                float2 r0v = *(const float2*)(res + (size_t)r0 * N + col);
                float2 r1v = *(const float2*)(res + (size_t)(r0 + 8) * N + col);
                v0.x += r0v.x; v0.y += r0v.y;
                v1.x += r1v.x; v1.y += r1v.y;
            }
            *(float2*)(C + (size_t)r0 * N + col) = v0;
            *(float2*)(C + (size_t)(r0 + 8) * N + col) = v1;
        }
    }
}

// ---------------- RMSNorm -> bf16 hi/lo planes (optional embed gather) ----------------
__global__ void rmsnorm_split_kernel(const float* __restrict__ x,
                                     const int* __restrict__ ids,
                                     const float* __restrict__ emb,
                                     const float* __restrict__ w,
                                     float* __restrict__ hout,
                                     __nv_bfloat16* __restrict__ hi,
                                     __nv_bfloat16* __restrict__ lo) {
    int row = blockIdx.x;
    const float4* xr;
    if (ids) {
        int tok = ids[row];
        xr = (const float4*)(emb + (size_t)tok * HID);
    } else {
        xr = (const float4*)(x + (size_t)row * HID);
    }
    const float4* wr = (const float4*)w;

    float4 v0 = xr[threadIdx.x];
    float4 v1 = xr[threadIdx.x + 256];
    if (hout) {
        ((float4*)(hout + (size_t)row * HID))[threadIdx.x] = v0;
        ((float4*)(hout + (size_t)row * HID))[threadIdx.x + 256] = v1;
    }
    float ss = v0.x * v0.x + v0.y * v0.y + v0.z * v0.z + v0.w * v0.w
             + v1.x * v1.x + v1.y * v1.y + v1.z * v1.z + v1.w * v1.w;

    __shared__ float red[8];
    for (int o = 16; o > 0; o >>= 1) ss += __shfl_down_sync(0xffffffffu, ss, o);
    if ((threadIdx.x & 31) == 0) red[threadIdx.x >> 5] = ss;
    __syncthreads();
    if (threadIdx.x < 8) {
        float t = red[threadIdx.x];
        for (int o = 4; o > 0; o >>= 1) t += __shfl_down_sync(0xffu, t, o);
        if (threadIdx.x == 0) red[0] = t;
    }
    __syncthreads();
    float inv = rsqrtf(red[0] / (float)HID + 1e-6f);

    float4 w0 = wr[threadIdx.x];
    float4 w1 = wr[threadIdx.x + 256];
    float4 o0, o1;
    o0.x = v0.x * inv * w0.x; o0.y = v0.y * inv * w0.y;
    o0.z = v0.z * inv * w0.z; o0.w = v0.w * inv * w0.w;
    o1.x = v1.x * inv * w1.x; o1.y = v1.y * inv * w1.y;
    o1.z = v1.z * inv * w1.z; o1.w = v1.w * inv * w1.w;
    uint2 h, l;
    size_t b = (size_t)row * (HID / 4);
    split4(o0, h, l);
    ((uint2*)hi)[b + threadIdx.x] = h;
    ((uint2*)lo)[b + threadIdx.x] = l;
    split4(o1, h, l);
    ((uint2*)hi)[b + threadIdx.x + 256] = h;
    ((uint2*)lo)[b + threadIdx.x + 256] = l;
}

// ---------------- RoPE (LUT): fp32 qkv -> rotated bf16 hi/lo planes ----------------
__global__ void rope_split_kernel(const float* __restrict__ qkv,
                                  const float* __restrict__ lut,
                                  __nv_bfloat16* __restrict__ hi,
                                  __nv_bfloat16* __restrict__ lo) {
    int s = blockIdx.x;
    int hh = blockIdx.y;
    int i = threadIdx.x;
    size_t base = (size_t)s * NQKV +
        ((hh < NHEAD) ? hh * HDIM
         : (hh < NHEAD + NKVH) ? HID + (hh - NHEAD) * HDIM
         : HID + NKVH * HDIM + (hh - NHEAD - NKVH) * HDIM);
    float x1 = qkv[base + i];
    float x2 = qkv[base + i + 64];
    float y1, y2;
    if (hh < NHEAD + NKVH) {
        float2 cs = ((const float2*)lut)[s * 64 + i];
        y1 = x1 * cs.x - x2 * cs.y;
        y2 = x2 * cs.x + x1 * cs.y;
    } else {
        y1 = x1; y2 = x2;
    }
    uint16_t h1, l1, h2, l2;
    split1(y1, h1, l1);
    split1(y2, h2, l2);
    ((uint16_t*)hi)[base + i]      = h1;
    ((uint16_t*)lo)[base + i]      = l1;
    ((uint16_t*)hi)[base + i + 64] = h2;
    ((uint16_t*)lo)[base + i + 64] = l2;
}

// ---------------- tensor-core flash attention (bf16x3, causal, GQA) ----------------
#define ATT_STRIDE 136
#define ATT_PLANE  (64 * ATT_STRIDE * 2)
#define ATT_SMEM   (6 * ATT_PLANE)

__global__ __launch_bounds__(128) void attn_mma_kernel(
    const __nv_bfloat16* __restrict__ qhi, const __nv_bfloat16* __restrict__ qlo,
    __nv_bfloat16* __restrict__ ohi, __nv_bfloat16* __restrict__ olo) {
    extern __shared__ char smc[];
    const uint32_t smb = smem_u32(smc);
    const uint32_t Qh = smb,            Ql = Qh + ATT_PLANE;
    const uint32_t Kh = Ql + ATT_PLANE, Kl = Kh + ATT_PLANE;
    const uint32_t Vh = Kl + ATT_PLANE, Vl = Vh + ATT_PLANE;

    const int head = blockIdx.x;
    const int qb   = blockIdx.y;
    const int kvh  = head >> 2;
    const int tid  = threadIdx.x;
    const int lane = tid & 31;
    const int warp = tid >> 5;

#pragma unroll
    for (int i = 0; i < 8; i++) {
        int id = tid + i * 128;
        int r = id >> 4, c = id & 15;
        uint32_t d = (uint32_t)(r * ATT_STRIDE * 2 + c * 16);
        size_t so = (size_t)(qb * 64 + r) * NQKV + head * HDIM + c * 8;
        CP16(Qh + d, qhi + so);
        CP16(Ql + d, qlo + so);
    }
    CP_COMMIT();

    float o[16][4];
#pragma unroll
    for (int t = 0; t < 16; t++)
#pragma unroll
        for (int q = 0; q < 4; q++) o[t][q] = 0.f;
    float mA = -1e30f, mB = -1e30f, lA = 0.f, lB = 0.f;

    const uint32_t qLd = (uint32_t)((warp * 16 + (lane & 15)) * ATT_STRIDE * 2 +
                                    ((lane >> 4) & 1) * 16);
    const uint32_t kLd = (uint32_t)((lane & 7) * ATT_STRIDE * 2 +
                                    ((lane >> 3) & 1) * 16);
    const uint32_t vLd = (uint32_t)((lane & 15) * ATT_STRIDE * 2 +
                                    ((lane >> 4) & 1) * 16);
    const float scale = 0.08838834764831845f;
    const int rowA = warp * 16 + (lane >> 2);
    const int rowB = rowA + 8;

    for (int kb = 0; kb <= qb; kb++) {
        __syncthreads();
#pragma unroll
        for (int i = 0; i < 8; i++) {
            int id = tid + i * 128;
            int r = id >> 4, c = id & 15;
            uint32_t d = (uint32_t)(r * ATT_STRIDE * 2 + c * 16);
            size_t ko = (size_t)(kb * 64 + r) * NQKV + HID + kvh * HDIM + c * 8;
            size_t vo = ko + NKVH * HDIM;
            CP16(Kh + d, qhi + ko);
            CP16(Kl + d, qlo + ko);
            CP16(Vh + d, qhi + vo);
            CP16(Vl + d, qlo + vo);
        }
        CP_COMMIT();
        asm volatile("cp.async.wait_group 0;" ::: "memory");
        __syncthreads();

        float s[8][4];
#pragma unroll
        for (int t = 0; t < 8; t++)
#pragma unroll
            for (int q = 0; q < 4; q++) s[t][q] = 0.f;
#pragma unroll
        for (int ds = 0; ds < 8; ds++) {
            uint32_t ah[4], al[4];
            ldsm_x4(ah, Qh + qLd + ds * 32);
            ldsm_x4(al, Ql + qLd + ds * 32);
#pragma unroll
            for (int nt = 0; nt < 8; nt++) {
                uint32_t ko = kLd + (uint32_t)(nt * 8 * ATT_STRIDE * 2 + ds * 32);
                uint32_t bh[2], bl[2];
                ldsm_x2(bh, Kh + ko);
                ldsm_x2(bl, Kl + ko);
                mma_bf16(s[nt], ah, bh);
                mma_bf16(s[nt], ah, bl);
                mma_bf16(s[nt], al, bh);
            }
        }

#pragma unroll
        for (int nt = 0; nt < 8; nt++) {
#pragma unroll
            for (int q = 0; q < 4; q++) s[nt][q] *= scale;
            if (kb == qb) {
                int c0 = nt * 8 + (lane & 3) * 2;
                if (c0 > rowA)     s[nt][0] = -1e9f;
                if (c0 + 1 > rowA) s[nt][1] = -1e9f;
                if (c0 > rowB)     s[nt][2] = -1e9f;
                if (c0 + 1 > rowB) s[nt][3] = -1e9f;
            }
        }

        float mxA = -1e30f, mxB = -1e30f;
#pragma unroll
        for (int nt = 0; nt < 8; nt++) {
            mxA = fmaxf(mxA, fmaxf(s[nt][0], s[nt][1]));
            mxB = fmaxf(mxB, fmaxf(s[nt][2], s[nt][3]));
        }
        mxA = fmaxf(mxA, __shfl_xor_sync(0xffffffffu, mxA, 1));
        mxA = fmaxf(mxA, __shfl_xor_sync(0xffffffffu, mxA, 2));
        mxB = fmaxf(mxB, __shfl_xor_sync(0xffffffffu, mxB, 1));
        mxB = fmaxf(mxB, __shfl_xor_sync(0xffffffffu, mxB, 2));
        float mAn = fmaxf(mA, mxA), mBn = fmaxf(mB, mxB);
        float aAf = expf(mA - mAn), aBf = expf(mB - mBn);
        float pA = 0.f, pB = 0.f;
#pragma unroll
        for (int nt = 0; nt < 8; nt++) {
            s[nt][0] = expf(s[nt][0] - mAn);
            s[nt][1] = expf(s[nt][1] - mAn);
            s[nt][2] = expf(s[nt][2] - mBn);
            s[nt][3] = expf(s[nt][3] - mBn);
            pA += s[nt][0] + s[nt][1];
            pB += s[nt][2] + s[nt][3];
        }
        pA += __shfl_xor_sync(0xffffffffu, pA, 1);
        pA += __shfl_xor_sync(0xffffffffu, pA, 2);
        pB += __shfl_xor_sync(0xffffffffu, pB, 1);
        pB += __shfl_xor_sync(0xffffffffu, pB, 2);
        lA = lA * aAf + pA;
        lB = lB * aBf + pB;
        mA = mAn;
        mB = mBn;
#pragma unroll
        for (int t = 0; t < 16; t++) {
            o[t][0] *= aAf; o[t][1] *= aAf;
            o[t][2] *= aBf; o[t][3] *= aBf;
        }

#pragma unroll
        for (int ks = 0; ks < 4; ks++) {
            uint32_t ph[4], pl[4];
            ph[0] = splitpack(s[2 * ks][0],     s[2 * ks][1],     pl[0]);
            ph[1] = splitpack(s[2 * ks][2],     s[2 * ks][3],     pl[1]);
            ph[2] = splitpack(s[2 * ks + 1][0], s[2 * ks + 1][1], pl[2]);
            ph[3] = splitpack(s[2 * ks + 1][2], s[2 * ks + 1][3], pl[3]);
#pragma unroll
            for (int dt = 0; dt < 8; dt++) {
                uint32_t vo = vLd + (uint32_t)(ks * 16 * ATT_STRIDE * 2 + dt * 32);
                uint32_t vh[4], vl[4];
                ldsm_x4t(vh, Vh + vo);
                ldsm_x4t(vl, Vl + vo);
#pragma unroll
                for (int h = 0; h < 2; h++) {
                    float* od = o[dt * 2 + h];
                    mma_bf16(od, ph, vh + 2 * h);
                    mma_bf16(od, ph, vl + 2 * h);
                    mma_bf16(od, pl, vh + 2 * h);
                }
            }
        }
    }

    float liA = 1.0f / lA, liB = 1.0f / lB;
    int gRowA = qb * 64 + rowA;
    int gRowB = qb * 64 + rowB;
#pragma unroll
    for (int nt = 0; nt < 16; nt++) {
        int col = head * HDIM + nt * 8 + (lane & 3) * 2;
        uint32_t hA, lAo, hB, lBo;
        hA = splitpack(o[nt][0] * liA, o[nt][1] * liA, lAo);
        hB = splitpack(o[nt][2] * liB, o[nt][3] * liB, lBo);
        size_t iA = ((size_t)gRowA * HID + col) >> 1;
        size_t iB = ((size_t)gRowB * HID + col) >> 1;
        ((uint32_t*)ohi)[iA] = hA;
        ((uint32_t*)olo)[iA] = lAo;
        ((uint32_t*)ohi)[iB] = hB;
        ((uint32_t*)olo)[iB] = lBo;
    }
}

// ---------------- SiLU from fused [2048,16384] gate|up buffer ----------------
__global__ void silu_split_kernel(const float* __restrict__ fused,
                                  __nv_bfloat16* __restrict__ hi,
                                  __nv_bfloat16* __restrict__ lo) {
    int i = blockIdx.x * blockDim.x + threadIdx.x;
    int row = i >> 11;
    int c4  = i & 2047;
    size_t base = (size_t)row * (NFF2 / 4);
    float4 gv = ((const float4*)fused)[base + c4];
    float4 uv = ((const float4*)fused)[base + (FFD / 4) + c4];
    gv.x = gv.x / (1.f + expf(-gv.x)) * uv.x;
    gv.y = gv.y / (1.f + expf(-gv.y)) * uv.y;
    gv.z = gv.z / (1.f + expf(-gv.z)) * uv.z;
    gv.w = gv.w / (1.f + expf(-gv.w)) * uv.w;
    uint2 h, l;
    split4(gv, h, l);
    ((uint2*)hi)[i] = h;
    ((uint2*)lo)[i] = l;
}

// ---------------- host orchestration ----------------
static __nv_bfloat16 *s_ahi, *s_alo, *s_whi, *s_wlo, *s_qhi, *s_qlo;

static void run_split(const float* src, size_t n) {
    int nT = (int)(n / 16);
    split_kernel<<<nT / 256, 256>>>(src, s_whi, s_wlo, nT);
}
static void run_gemm(const float* b0, const float* b1, const float* b2,
                     const float* res, float* C, int M, int N, int K) {
    if (N >= 8192 || K >= 8192) {
        dim3 grid(N / 128, M / 256);
        gemm_big_kernel<<<grid, 512, BIG_SMEM>>>(
            s_ahi, s_alo, s_whi, s_wlo, b0, res, C, M, N, K);
    } else {
        dim3 grid(N / 128, M / 128);
        gemm_sml_kernel<<<grid, 256, SML_SMEM>>>(
            s_ahi, s_alo, s_whi, s_wlo, b0, b1, b2, res, C, M, N, K);
    }
}

extern "C" void kernel_launch(void* const* d_in, const int* in_sizes, int n_in,
                              void* d_out, int out_size) {
    const int*   ids    = (const int*)d_in[0];
    const float* emb    = (const float*)d_in[1];
    const float* Wq     = (const float*)d_in[2];
    const float* bq     = (const float*)d_in[3];
    const float* Wk     = (const float*)d_in[4];
    const float* bk     = (const float*)d_in[5];
    const float* Wv     = (const float*)d_in[6];
    const float* bv     = (const float*)d_in[7];
    const float* Wo     = (const float*)d_in[8];
    const float* ln1    = (const float*)d_in[9];
    const float* ln2    = (const float*)d_in[10];
    const float* Wg     = (const float*)d_in[11];
    const float* Wu     = (const float*)d_in[12];
    const float* Wd     = (const float*)d_in[13];
    const float* norm_w = (const float*)d_in[14];
    const float* Wlm    = (const float*)d_in[15];
    const float* blm    = (const float*)d_in[16];
    float* out = (float*)d_out;

    float* base = nullptr;
    float* rope_lut = nullptr;
    cudaGetSymbolAddress((void**)&base, g_scratch);
    cudaGetSymbolAddress((void**)&rope_lut, g_rope);
    cudaGetSymbolAddress((void**)&s_ahi, g_ahi);
    cudaGetSymbolAddress((void**)&s_alo, g_alo);
    cudaGetSymbolAddress((void**)&s_whi, g_whi);
    cudaGetSymbolAddress((void**)&s_wlo, g_wlo);
    cudaGetSymbolAddress((void**)&s_qhi, g_qkvhi);
    cudaGetSymbolAddress((void**)&s_qlo, g_qkvlo);

    float* hbuf  = base;
    float* qkv   = base + (size_t)SH;
    float* fbuf  = qkv + (size_t)SQ * NQKV;

    cudaFuncSetAttribute(attn_mma_kernel,
                         cudaFuncAttributeMaxDynamicSharedMemorySize, ATT_SMEM);
    cudaFuncSetAttribute(gemm_sml_kernel,
                         cudaFuncAttributeMaxDynamicSharedMemorySize, SML_SMEM);
    cudaFuncSetAttribute(gemm_big_kernel,
                         cudaFuncAttributeMaxDynamicSharedMemorySize, BIG_SMEM);

    rope_lut_kernel<<<SQ, 64>>>(rope_lut);

    for (int l = 0; l < NLAYER; l++) {
        const float* Wql = Wq + (size_t)l * HID * HID;
        const float* bql = bq + (size_t)l * HID;
        const float* Wkl = Wk + (size_t)l * HID * (NKVH * HDIM);
        const float* bkl = bk + (size_t)l * (NKVH * HDIM);
        const float* Wvl = Wv + (size_t)l * HID * (NKVH * HDIM);
        const float* bvl = bv + (size_t)l * (NKVH * HDIM);
        const float* Wol = Wo + (size_t)l * HID * HID;
        const float* l1  = ln1 + (size_t)l * HID;
        const float* l2  = ln2 + (size_t)l * HID;
        const float* Wgl = Wg + (size_t)l * HID * FFD;
        const float* Wul = Wu + (size_t)l * HID * FFD;
        const float* Wdl = Wd + (size_t)l * FFD * HID;

        // ---- fused QKV projection ----
        {
            int nT = (int)((size_t)HID * HID / 16);
            split2d_kernel<<<nT / 256, 256>>>(
                Wql, s_whi, s_wlo, HID / 8, NQKV / 8, nT);
        }
        {
            int nT = HID * 1024 / 16;
            splitkv_kernel<<<nT / 256, 256>>>(Wkl, Wvl, s_whi, s_wlo, nT);
        }
        if (l == 0)
            rmsnorm_split_kernel<<<SQ, 256>>>(nullptr, ids, emb, l1, hbuf,
                                              s_ahi, s_alo);
        else
            rmsnorm_split_kernel<<<SQ, 256>>>(hbuf, nullptr, nullptr, l1,
                                              nullptr, s_ahi, s_alo);
        run_gemm(bql, bkl, bvl, nullptr, qkv, SQ, NQKV, HID);

        // ---- RoPE + split (LUT) ----
        dim3 rgrid(SQ, NHEAD + 2 * NKVH);
        rope_split_kernel<<<rgrid, 64>>>(qkv, rope_lut, s_qhi, s_qlo);

        // ---- attention -> activation planes ----
        dim3 agrid(NHEAD, SQ / 64);
        attn_mma_kernel<<<agrid, 128, ATT_SMEM>>>(s_qhi, s_qlo, s_ahi, s_alo);

        // ---- O projection (+residual) ----
        run_split(Wol, (size_t)HID * HID);
        run_gemm(nullptr, nullptr, nullptr, hbuf, hbuf, SQ, HID, HID);

        // ---- fused gate|up MLP (contiguous halves) ----
        rmsnorm_split_kernel<<<SQ, 256>>>(hbuf, nullptr, nullptr, l2,
                                          nullptr, s_ahi, s_alo);
        {
            int nT = (int)((size_t)HID * FFD / 16);
            split2d_kernel<<<nT / 256, 256>>>(
                Wgl, s_whi, s_wlo, FFD / 8, NFF2 / 8, nT);
            split2d_kernel<<<nT / 256, 256>>>(
                Wul, s_whi + FFD, s_wlo + FFD, FFD / 8, NFF2 / 8, nT);
        }
        run_gemm(nullptr, nullptr, nullptr, nullptr, fbuf, SQ, NFF2, HID);
        silu_split_kernel<<<SFF / 4 / 256, 256>>>(fbuf, s_ahi, s_alo);
        run_split(Wdl, (size_t)FFD * HID);
        run_gemm(nullptr, nullptr, nullptr, hbuf, hbuf, SQ, HID, FFD);
    }

    rmsnorm_split_kernel<<<SQ, 256>>>(hbuf, nullptr, nullptr, norm_w,
                                      nullptr, s_ahi, s_alo);
    run_split(Wlm, (size_t)HID * VOC);
    run_gemm(blm, nullptr, nullptr, nullptr, out, SQ, VOC, HID);
}

// round 16
// speedup vs baseline: 1.0795x; 1.0172x over previous
#include <cuda_runtime.h>
#include <cuda_bf16.h>
#include <math.h>
#include <cstdint>

// ---------------- problem constants ----------------
#define SQ     2048
#define HID    2048
#define VOC    32000
#define NHEAD  16
#define NKVH   4
#define HDIM   128
#define FFD    8192
#define NLAYER 4
#define NQKV   3072   // 2048 + 512 + 512
#define NFF2   16384  // fused gate|up (contiguous halves)

#define SH  (SQ * HID)
#define SFF (SQ * FFD)

__device__ float g_scratch[(size_t)SH + (size_t)SQ * NQKV + 2 * (size_t)SFF];
__device__ __nv_bfloat16 g_ahi[(size_t)SFF];
__device__ __nv_bfloat16 g_alo[(size_t)SFF];
__device__ __nv_bfloat16 g_whi[(size_t)HID * VOC];
__device__ __nv_bfloat16 g_wlo[(size_t)HID * VOC];
__device__ __nv_bfloat16 g_qkvhi[(size_t)SQ * NQKV];
__device__ __nv_bfloat16 g_qkvlo[(size_t)SQ * NQKV];
__device__ float g_rope[SQ * 64 * 2];   // cos|sin per (pos, freq)

// ======================= helpers =======================
__device__ __forceinline__ uint32_t smem_u32(const void* p) {
    uint32_t a;
    asm("{ .reg .u64 t; cvta.to.shared.u64 t, %1; cvt.u32.u64 %0, t; }"
        : "=r"(a) : "l"(p));
    return a;
}
__device__ __forceinline__ void ldsm_x4(uint32_t* r, uint32_t addr) {
    asm volatile("ldmatrix.sync.aligned.m8n8.x4.shared.b16 {%0,%1,%2,%3}, [%4];"
                 : "=r"(r[0]), "=r"(r[1]), "=r"(r[2]), "=r"(r[3]) : "r"(addr));
}
__device__ __forceinline__ void ldsm_x2(uint32_t* r, uint32_t addr) {
    asm volatile("ldmatrix.sync.aligned.m8n8.x2.shared.b16 {%0,%1}, [%2];"
                 : "=r"(r[0]), "=r"(r[1]) : "r"(addr));
}
__device__ __forceinline__ void ldsm_x4t(uint32_t* r, uint32_t addr) {
    asm volatile("ldmatrix.sync.aligned.m8n8.x4.trans.shared.b16 {%0,%1,%2,%3}, [%4];"
                 : "=r"(r[0]), "=r"(r[1]), "=r"(r[2]), "=r"(r[3]) : "r"(addr));
}
__device__ __forceinline__ void mma_bf16(float* c, const uint32_t* a,
                                         const uint32_t* b) {
    asm volatile("mma.sync.aligned.m16n8k16.row.col.f32.bf16.bf16.f32 "
                 "{%0,%1,%2,%3}, {%4,%5,%6,%7}, {%8,%9}, {%0,%1,%2,%3};"
                 : "+f"(c[0]), "+f"(c[1]), "+f"(c[2]), "+f"(c[3])
                 : "r"(a[0]), "r"(a[1]), "r"(a[2]), "r"(a[3]),
                   "r"(b[0]), "r"(b[1]));
}
__device__ __forceinline__ uint32_t pack2(__nv_bfloat16 a, __nv_bfloat16 b) {
    uint16_t ua = *(uint16_t*)&a, ub = *(uint16_t*)&b;
    return ((uint32_t)ub << 16) | (uint32_t)ua;
}
__device__ __forceinline__ void split4(float4 f, uint2& hi, uint2& lo) {
    __nv_bfloat16 hx = __float2bfloat16_rn(f.x);
    __nv_bfloat16 hy = __float2bfloat16_rn(f.y);
    __nv_bfloat16 hz = __float2bfloat16_rn(f.z);
    __nv_bfloat16 hw = __float2bfloat16_rn(f.w);
    __nv_bfloat16 lx = __float2bfloat16_rn(f.x - __bfloat162float(hx));
    __nv_bfloat16 ly = __float2bfloat16_rn(f.y - __bfloat162float(hy));
    __nv_bfloat16 lz = __float2bfloat16_rn(f.z - __bfloat162float(hz));
    __nv_bfloat16 lw = __float2bfloat16_rn(f.w - __bfloat162float(hw));
    hi = make_uint2(pack2(hx, hy), pack2(hz, hw));
    lo = make_uint2(pack2(lx, ly), pack2(lz, lw));
}
__device__ __forceinline__ void split1(float x, uint16_t& h, uint16_t& l) {
    __nv_bfloat16 hb = __float2bfloat16_rn(x);
    __nv_bfloat16 lb = __float2bfloat16_rn(x - __bfloat162float(hb));
    h = *(uint16_t*)&hb;
    l = *(uint16_t*)&lb;
}
__device__ __forceinline__ uint32_t splitpack(float a, float b, uint32_t& lo) {
    uint16_t ha, la, hb, lb;
    split1(a, ha, la);
    split1(b, hb, lb);
    lo = ((uint32_t)lb << 16) | la;
    return ((uint32_t)hb << 16) | ha;
}
#define CP16(dst, src) \
    asm volatile("cp.async.cg.shared.global [%0], [%1], 16;" :: "r"(dst), "l"(src))
#define CP_COMMIT() asm volatile("cp.async.commit_group;" ::: "memory")

// ---------------- weight splits ----------------
__global__ void split_kernel(const float* __restrict__ src,
                             __nv_bfloat16* __restrict__ hi,
                             __nv_bfloat16* __restrict__ lo, int nT) {
    int i = blockIdx.x * blockDim.x + threadIdx.x;
    float4 f[4];
#pragma unroll
    for (int j = 0; j < 4; j++) f[j] = ((const float4*)src)[4 * i + j];
    uint2 h[4], l[4];
#pragma unroll
    for (int j = 0; j < 4; j++) split4(f[j], h[j], l[j]);
    ((uint4*)hi)[2 * i]     = make_uint4(h[0].x, h[0].y, h[1].x, h[1].y);
    ((uint4*)hi)[2 * i + 1] = make_uint4(h[2].x, h[2].y, h[3].x, h[3].y);
    ((uint4*)lo)[2 * i]     = make_uint4(l[0].x, l[0].y, l[1].x, l[1].y);
    ((uint4*)lo)[2 * i + 1] = make_uint4(l[2].x, l[2].y, l[3].x, l[3].y);
}
__global__ void split2d_kernel(const float* __restrict__ src,
                               __nv_bfloat16* __restrict__ hi,
                               __nv_bfloat16* __restrict__ lo,
                               int n8row, int ld8, int nT) {
    int i = blockIdx.x * blockDim.x + threadIdx.x;
    int g = 2 * i;
    int r = g / n8row, c8 = g - r * n8row;
    float4 f[4];
#pragma unroll
    for (int j = 0; j < 4; j++) f[j] = ((const float4*)src)[4 * i + j];
    uint2 h[4], l[4];
#pragma unroll
    for (int j = 0; j < 4; j++) split4(f[j], h[j], l[j]);
    size_t o = (size_t)r * ld8 + c8;
    ((uint4*)hi)[o]     = make_uint4(h[0].x, h[0].y, h[1].x, h[1].y);
    ((uint4*)hi)[o + 1] = make_uint4(h[2].x, h[2].y, h[3].x, h[3].y);
    ((uint4*)lo)[o]     = make_uint4(l[0].x, l[0].y, l[1].x, l[1].y);
    ((uint4*)lo)[o + 1] = make_uint4(l[2].x, l[2].y, l[3].x, l[3].y);
}
__global__ void splitkv_kernel(const float* __restrict__ Wk,
                               const float* __restrict__ Wv,
                               __nv_bfloat16* __restrict__ hi,
                               __nv_bfloat16* __restrict__ lo, int nT) {
    int i = blockIdx.x * blockDim.x + threadIdx.x;
    int g0 = 2 * i;
    int r  = g0 >> 7;
    int c0 = g0 & 127;
#pragma unroll
    for (int t = 0; t < 2; t++) {
        int c = c0 + t;
        const float* s = (c < 64) ? Wk + (size_t)r * 512 + c * 8
                                  : Wv + (size_t)r * 512 + (c - 64) * 8;
        float4 f0 = ((const float4*)s)[0];
        float4 f1 = ((const float4*)s)[1];
        uint2 h0, l0, h1, l1;
        split4(f0, h0, l0);
        split4(f1, h1, l1);
        size_t o = (size_t)r * (NQKV / 8) + (HID / 8) + c;
        ((uint4*)hi)[o] = make_uint4(h0.x, h0.y, h1.x, h1.y);
        ((uint4*)lo)[o] = make_uint4(l0.x, l0.y, l1.x, l1.y);
    }
}

// ---------------- RoPE LUT (once per forward) ----------------
__global__ void rope_lut_kernel(float* __restrict__ lut) {
    int s = blockIdx.x;
    int i = threadIdx.x;
    float inv = powf(1000000.0f, -(float)i / 64.0f);
    float f = (float)s * inv;
    lut[(s * 64 + i) * 2]     = cosf(f);
    lut[(s * 64 + i) * 2 + 1] = sinf(f);
}

// ======================= BM=128 GEMM (R9-proven) =======================
#define SST_A_LO 10240u
#define SST_B_HI 20480u
#define SST_B_LO 30208u
#define SSTAGE   39936u
#define SML_SMEM (2 * 39936)

__global__ __launch_bounds__(256, 2)
void gemm_sml_kernel(const __nv_bfloat16* __restrict__ Ahi,
                     const __nv_bfloat16* __restrict__ Alo,
                     const __nv_bfloat16* __restrict__ Whi,
                     const __nv_bfloat16* __restrict__ Wlo,
                     const float* __restrict__ b0, const float* __restrict__ b1,
                     const float* __restrict__ b2, const float* __restrict__ res,
                     float* __restrict__ C, int M, int N, int K) {
    extern __shared__ char sm[];
    const uint32_t smb = smem_u32(sm);
    const int tid  = threadIdx.x;
    const int lane = tid & 31;
    const int warp = tid >> 5;
    const int wm = warp & 3;
    const int wn = warp >> 2;
    const int bm = blockIdx.y * 128;
    const int bn = blockIdx.x * 128;

    const uint32_t aLd = (uint32_t)((wm * 32 + (lane & 15)) * 80 +
                                    ((lane >> 4) & 1) * 16);
    const uint32_t bLd = (uint32_t)((lane & 15) * 304 + (lane >> 4) * 16 +
                                    wn * 128);

    float acc[2][8][4];
#pragma unroll
    for (int i = 0; i < 2; i++)
#pragma unroll
        for (int j = 0; j < 8; j++)
#pragma unroll
            for (int q = 0; q < 4; q++) acc[i][j][q] = 0.f;

    const int nc = K >> 5;

    auto issue = [&](int c, int stg) {
        if (c < nc) {
            const uint32_t st = smb + (uint32_t)stg * SSTAGE;
            const size_t kof = (size_t)c * 32;
#pragma unroll
            for (int i = 0; i < 2; i++) {
                int id = tid + i * 256;
                int r = id >> 2, cc = id & 3;
                uint32_t d = st + (uint32_t)(r * 80 + cc * 16);
                size_t so = (size_t)(bm + r) * K + kof + cc * 8;
                CP16(d, Ahi + so);
                CP16(d + SST_A_LO, Alo + so);
            }
#pragma unroll
            for (int i = 0; i < 2; i++) {
                int id = tid + i * 256;
                int kr = id >> 4, ncc = id & 15;
                uint32_t d = st + SST_B_HI + (uint32_t)(kr * 304 + ncc * 16);
                size_t so = (size_t)(kof + kr) * N + bn + ncc * 8;
                CP16(d, Whi + so);
                CP16(d + 9728u, Wlo + so);
            }
        }
        CP_COMMIT();
    };

    issue(0, 0);

    for (int c = 0; c < nc; c++) {
        asm volatile("cp.async.wait_group 0;" ::: "memory");
        __syncthreads();
        issue(c + 1, (c + 1) & 1);
        const uint32_t sb = smb + (uint32_t)(c & 1) * SSTAGE;
#pragma unroll
        for (int ks = 0; ks < 2; ks++) {
            uint32_t ah[2][4], al[2][4];
#pragma unroll
            for (int tm = 0; tm < 2; tm++) {
                uint32_t off = aLd + (uint32_t)(tm * 16 * 80 + ks * 32);
                ldsm_x4(ah[tm], sb + off);
                ldsm_x4(al[tm], sb + SST_A_LO + off);
            }
            uint32_t bh[2][4], bl[2][4];
            {
                uint32_t off = bLd + (uint32_t)(ks * 16 * 304);
                ldsm_x4t(bh[0], sb + SST_B_HI + off);
                ldsm_x4t(bl[0], sb + SST_B_LO + off);
            }
#pragma unroll
            for (int p = 0; p < 4; p++) {
                const int cur = p & 1, nxt = cur ^ 1;
                if (p < 3) {
                    uint32_t off = bLd + (uint32_t)(ks * 16 * 304 + (p + 1) * 32);
                    ldsm_x4t(bh[nxt], sb + SST_B_HI + off);
                    ldsm_x4t(bl[nxt], sb + SST_B_LO + off);
                }
#pragma unroll
                for (int h = 0; h < 2; h++) {
#pragma unroll
                    for (int tm = 0; tm < 2; tm++) {
                        mma_bf16(acc[tm][p * 2 + h], ah[tm], bh[cur] + 2 * h);
                        mma_bf16(acc[tm][p * 2 + h], ah[tm], bl[cur] + 2 * h);
                        mma_bf16(acc[tm][p * 2 + h], al[tm], bh[cur] + 2 * h);
                    }
                }
            }
        }
    }

#pragma unroll
    for (int tm = 0; tm < 2; tm++) {
#pragma unroll
        for (int bt = 0; bt < 8; bt++) {
            int r0  = bm + wm * 32 + tm * 16 + (lane >> 2);
            int col = bn + wn * 64 + bt * 8 + (lane & 3) * 2;
            float2 v0 = make_float2(acc[tm][bt][0], acc[tm][bt][1]);
            float2 v1 = make_float2(acc[tm][bt][2], acc[tm][bt][3]);
            if (b0) {
                const float* bp; int cc;
                if (col < 2048)      { bp = b0; cc = col; }
                else if (col < 2560) { bp = b1; cc = col - 2048; }
                else                 { bp = b2; cc = col - 2560; }
                float2 bb = *(const float2*)(bp + cc);
                v0.x += bb.x; v0.y += bb.y;
                v1.x += bb.x; v1.y += bb.y;
            }
            if (res) {
                float2 r0v = *(const float2*)(res + (size_t)r0 * N + col);
                float2 r1v = *(const float2*)(res + (size_t)(r0 + 8) * N + col);
                v0.x += r0v.x; v0.y += r0v.y;
                v1.x += r1v.x; v1.y += r1v.y;
            }
            *(float2*)(C + (size_t)r0 * N + col) = v0;
            *(float2*)(C + (size_t)(r0 + 8) * N + col) = v1;
        }
    }
}

// ======================= BM=256 big GEMM (R8-proven) =======================
#define BST_A_LO 20480u
#define BST_B_HI 40960u
#define BST_B_LO 50688u
#define BSTAGE   60416u
#define BIG_SMEM (3 * 60416)

__global__ __launch_bounds__(512, 1)
void gemm_big_kernel(const __nv_bfloat16* __restrict__ Ahi,
                     const __nv_bfloat16* __restrict__ Alo,
                     const __nv_bfloat16* __restrict__ Whi,
                     const __nv_bfloat16* __restrict__ Wlo,
                     const float* __restrict__ bias, const float* __restrict__ res,
                     float* __restrict__ C, int M, int N, int K) {
    extern __shared__ char sm[];
    const uint32_t smb = smem_u32(sm);
    const int tid  = threadIdx.x;
    const int lane = tid & 31;
    const int warp = tid >> 5;
    const int wm = warp & 7;
    const int wn = warp >> 3;
    const int bm = blockIdx.y * 256;
    const int bn = blockIdx.x * 128;

    const uint32_t aLd = (uint32_t)((wm * 32 + (lane & 15)) * 80 +
                                    ((lane >> 4) & 1) * 16);
    const uint32_t bLd = (uint32_t)((lane & 15) * 304 + (lane >> 4) * 16 +
                                    wn * 128);

    float acc[2][8][4];
#pragma unroll
    for (int i = 0; i < 2; i++)
#pragma unroll
        for (int j = 0; j < 8; j++)
#pragma unroll
            for (int q = 0; q < 4; q++) acc[i][j][q] = 0.f;

    const int nc = K >> 5;

    auto issue = [&](int c, int stg) {
        if (c < nc) {
            const uint32_t st = smb + (uint32_t)stg * BSTAGE;
            const size_t kof = (size_t)c * 32;
#pragma unroll
            for (int i = 0; i < 2; i++) {
                int id = tid + i * 512;
                int r = id >> 2, cc = id & 3;
                uint32_t d = st + (uint32_t)(r * 80 + cc * 16);
                size_t so = (size_t)(bm + r) * K + kof + cc * 8;
                CP16(d, Ahi + so);
                CP16(d + BST_A_LO, Alo + so);
            }
            {
                int kr = tid >> 4, ncc = tid & 15;
                uint32_t d = st + BST_B_HI + (uint32_t)(kr * 304 + ncc * 16);
                size_t so = (size_t)(kof + kr) * N + bn + ncc * 8;
                CP16(d, Whi + so);
                CP16(d + 9728u, Wlo + so);
            }
        }
        CP_COMMIT();
    };

    issue(0, 0);
    issue(1, 1);

    for (int c = 0; c < nc; c++) {
        asm volatile("cp.async.wait_group 1;" ::: "memory");
        __syncthreads();
        issue(c + 2, (c + 2) % 3);
        const uint32_t sb = smb + (uint32_t)(c % 3) * BSTAGE;
#pragma unroll
        for (int ks = 0; ks < 2; ks++) {
            uint32_t ah[2][4], al[2][4];
#pragma unroll
            for (int tm = 0; tm < 2; tm++) {
                uint32_t off = aLd + (uint32_t)(tm * 16 * 80 + ks * 32);
                ldsm_x4(ah[tm], sb + off);
                ldsm_x4(al[tm], sb + BST_A_LO + off);
            }
            uint32_t bh[2][4], bl[2][4];
            {
                uint32_t off = bLd + (uint32_t)(ks * 16 * 304);
                ldsm_x4t(bh[0], sb + BST_B_HI + off);
                ldsm_x4t(bl[0], sb + BST_B_LO + off);
            }
#pragma unroll
            for (int p = 0; p < 4; p++) {
                const int cur = p & 1, nxt = cur ^ 1;
                if (p < 3) {
                    uint32_t off = bLd + (uint32_t)(ks * 16 * 304 + (p + 1) * 32);
                    ldsm_x4t(bh[nxt], sb + BST_B_HI + off);
                    ldsm_x4t(bl[nxt], sb + BST_B_LO + off);
                }
#pragma unroll
                for (int h = 0; h < 2; h++) {
#pragma unroll
                    for (int tm = 0; tm < 2; tm++) {
                        mma_bf16(acc[tm][p * 2 + h], ah[tm], bh[cur] + 2 * h);
                        mma_bf16(acc[tm][p * 2 + h], ah[tm], bl[cur] + 2 * h);
                        mma_bf16(acc[tm][p * 2 + h], al[tm], bh[cur] + 2 * h);
                    }
                }
            }
        }
    }

#pragma unroll
    for (int tm = 0; tm < 2; tm++) {
#pragma unroll
        for (int bt = 0; bt < 8; bt++) {
            int r0  = bm + wm * 32 + tm * 16 + (lane >> 2);
            int col = bn + wn * 64 + bt * 8 + (lane & 3) * 2;
            float2 v0 = make_float2(acc[tm][bt][0], acc[tm][bt][1]);
            float2 v1 = make_float2(acc[tm][bt][2], acc[tm][bt][3]);
            if (bias) {
                float2 bb = *(const float2*)(bias + col);
                v0.x += bb.x; v0.y += bb.y;
                v1.x += bb.x; v1.y += bb.y;
            }
            if (res) {
                float2 r0v = *(const float2*)(res + (size_t)r0 * N + col);
                float2 r1v = *(const float2*)(res + (size_t)(r0 + 8) * N + col);
                v0.x += r0v.x; v0.y += r0v.y;
                v1.x += r1v.x; v1.y += r1v.y;
            }
            *(float2*)(C + (size_t)r0 * N + col) = v0;
            *(float2*)(C + (size_t)(r0 + 8) * N + col) = v1;
        }
    }
}

// ---------------- RMSNorm -> bf16 hi/lo planes (optional embed gather) ----------------
__global__ void rmsnorm_split_kernel(const float* __restrict__ x,
                                     const int* __restrict__ ids,
                                     const float* __restrict__ emb,
                                     const float* __restrict__ w,
                                     float* __restrict__ hout,
                                     __nv_bfloat16* __restrict__ hi,
                                     __nv_bfloat16* __restrict__ lo) {
    int row = blockIdx.x;
    const float4* xr;
    if (ids) {
        int tok = ids[row];
        xr = (const float4*)(emb + (size_t)tok * HID);
    } else {
        xr = (const float4*)(x + (size_t)row * HID);
    }
    const float4* wr = (const float4*)w;

    float4 v0 = xr[threadIdx.x];
    float4 v1 = xr[threadIdx.x + 256];
    if (hout) {
        ((float4*)(hout + (size_t)row * HID))[threadIdx.x] = v0;
        ((float4*)(hout + (size_t)row * HID))[threadIdx.x + 256] = v1;
    }
    float ss = v0.x * v0.x + v0.y * v0.y + v0.z * v0.z + v0.w * v0.w
             + v1.x * v1.x + v1.y * v1.y + v1.z * v1.z + v1.w * v1.w;

    __shared__ float red[8];
    for (int o = 16; o > 0; o >>= 1) ss += __shfl_down_sync(0xffffffffu, ss, o);
    if ((threadIdx.x & 31) == 0) red[threadIdx.x >> 5] = ss;
    __syncthreads();
    if (threadIdx.x < 8) {
        float t = red[threadIdx.x];
        for (int o = 4; o > 0; o >>= 1) t += __shfl_down_sync(0xffu, t, o);
        if (threadIdx.x == 0) red[0] = t;
    }
    __syncthreads();
    float inv = rsqrtf(red[0] / (float)HID + 1e-6f);

    float4 w0 = wr[threadIdx.x];
    float4 w1 = wr[threadIdx.x + 256];
    float4 o0, o1;
    o0.x = v0.x * inv * w0.x; o0.y = v0.y * inv * w0.y;
    o0.z = v0.z * inv * w0.z; o0.w = v0.w * inv * w0.w;
    o1.x = v1.x * inv * w1.x; o1.y = v1.y * inv * w1.y;
    o1.z = v1.z * inv * w1.z; o1.w = v1.w * inv * w1.w;
    uint2 h, l;
    size_t b = (size_t)row * (HID / 4);
    split4(o0, h, l);
    ((uint2*)hi)[b + threadIdx.x] = h;
    ((uint2*)lo)[b + threadIdx.x] = l;
    split4(o1, h, l);
    ((uint2*)hi)[b + threadIdx.x + 256] = h;
    ((uint2*)lo)[b + threadIdx.x + 256] = l;
}

// ---------------- RoPE (LUT): fp32 qkv -> rotated bf16 hi/lo planes ----------------
__global__ void rope_split_kernel(const float* __restrict__ qkv,
                                  const float* __restrict__ lut,
                                  __nv_bfloat16* __restrict__ hi,
                                  __nv_bfloat16* __restrict__ lo) {
    int s = blockIdx.x;
    int hh = blockIdx.y;
    int i = threadIdx.x;
    size_t base = (size_t)s * NQKV +
        ((hh < NHEAD) ? hh * HDIM
         : (hh < NHEAD + NKVH) ? HID + (hh - NHEAD) * HDIM
         : HID + NKVH * HDIM + (hh - NHEAD - NKVH) * HDIM);
    float x1 = qkv[base + i];
    float x2 = qkv[base + i + 64];
    float y1, y2;
    if (hh < NHEAD + NKVH) {
        float2 cs = ((const float2*)lut)[s * 64 + i];
        y1 = x1 * cs.x - x2 * cs.y;
        y2 = x2 * cs.x + x1 * cs.y;
    } else {
        y1 = x1; y2 = x2;
    }
    uint16_t h1, l1, h2, l2;
    split1(y1, h1, l1);
    split1(y2, h2, l2);
    ((uint16_t*)hi)[base + i]      = h1;
    ((uint16_t*)lo)[base + i]      = l1;
    ((uint16_t*)hi)[base + i + 64] = h2;
    ((uint16_t*)lo)[base + i + 64] = l2;
}

// ---------------- tensor-core flash attention (bf16x3, causal, GQA) ----------------
// Longest-first scheduling: qb = gridDim.y-1-blockIdx.y so 32-iteration CTAs
// launch first (LPT packing; shortest-last tail).
#define ATT_STRIDE 136
#define ATT_PLANE  (64 * ATT_STRIDE * 2)
#define ATT_SMEM   (6 * ATT_PLANE)

__global__ __launch_bounds__(128) void attn_mma_kernel(
    const __nv_bfloat16* __restrict__ qhi, const __nv_bfloat16* __restrict__ qlo,
    __nv_bfloat16* __restrict__ ohi, __nv_bfloat16* __restrict__ olo) {
    extern __shared__ char smc[];
    const uint32_t smb = smem_u32(smc);
    const uint32_t Qh = smb,            Ql = Qh + ATT_PLANE;
    const uint32_t Kh = Ql + ATT_PLANE, Kl = Kh + ATT_PLANE;
    const uint32_t Vh = Kl + ATT_PLANE, Vl = Vh + ATT_PLANE;

    const int head = blockIdx.x;
    const int qb   = (int)gridDim.y - 1 - (int)blockIdx.y;   // LPT order
    const int kvh  = head >> 2;
    const int tid  = threadIdx.x;
    const int lane = tid & 31;
    const int warp = tid >> 5;

#pragma unroll
    for (int i = 0; i < 8; i++) {
        int id = tid + i * 128;
        int r = id >> 4, c = id & 15;
        uint32_t d = (uint32_t)(r * ATT_STRIDE * 2 + c * 16);
        size_t so = (size_t)(qb * 64 + r) * NQKV + head * HDIM + c * 8;
        CP16(Qh + d, qhi + so);
        CP16(Ql + d, qlo + so);
    }
    CP_COMMIT();

    float o[16][4];
#pragma unroll
    for (int t = 0; t < 16; t++)
#pragma unroll
        for (int q = 0; q < 4; q++) o[t][q] = 0.f;
    float mA = -1e30f, mB = -1e30f, lA = 0.f, lB = 0.f;

    const uint32_t qLd = (uint32_t)((warp * 16 + (lane & 15)) * ATT_STRIDE * 2 +
                                    ((lane >> 4) & 1) * 16);
    const uint32_t kLd = (uint32_t)((lane & 7) * ATT_STRIDE * 2 +
                                    ((lane >> 3) & 1) * 16);
    const uint32_t vLd = (uint32_t)((lane & 15) * ATT_STRIDE * 2 +
                                    ((lane >> 4) & 1) * 16);
    const float scale = 0.08838834764831845f;
    const int rowA = warp * 16 + (lane >> 2);
    const int rowB = rowA + 8;

    for (int kb = 0; kb <= qb; kb++) {
        __syncthreads();
#pragma unroll
        for (int i = 0; i < 8; i++) {
            int id = tid + i * 128;
            int r = id >> 4, c = id & 15;
            uint32_t d = (uint32_t)(r * ATT_STRIDE * 2 + c * 16);
            size_t ko = (size_t)(kb * 64 + r) * NQKV + HID + kvh * HDIM + c * 8;
            size_t vo = ko + NKVH * HDIM;
            CP16(Kh + d, qhi + ko);
            CP16(Kl + d, qlo + ko);
            CP16(Vh + d, qhi + vo);
            CP16(Vl + d, qlo + vo);
        }
        CP_COMMIT();
        asm volatile("cp.async.wait_group 0;" ::: "memory");
        __syncthreads();

        float s[8][4];
#pragma unroll
        for (int t = 0; t < 8; t++)
#pragma unroll
            for (int q = 0; q < 4; q++) s[t][q] = 0.f;
#pragma unroll
        for (int ds = 0; ds < 8; ds++) {
            uint32_t ah[4], al[4];
            ldsm_x4(ah, Qh + qLd + ds * 32);
            ldsm_x4(al, Ql + qLd + ds * 32);
#pragma unroll
            for (int nt = 0; nt < 8; nt++) {
                uint32_t ko = kLd + (uint32_t)(nt * 8 * ATT_STRIDE * 2 + ds * 32);
                uint32_t bh[2], bl[2];
                ldsm_x2(bh, Kh + ko);
                ldsm_x2(bl, Kl + ko);
                mma_bf16(s[nt], ah, bh);
                mma_bf16(s[nt], ah, bl);
                mma_bf16(s[nt], al, bh);
            }
        }

#pragma unroll
        for (int nt = 0; nt < 8; nt++) {
#pragma unroll
            for (int q = 0; q < 4; q++) s[nt][q] *= scale;
            if (kb == qb) {
                int c0 = nt * 8 + (lane & 3) * 2;
                if (c0 > rowA)     s[nt][0] = -1e9f;
                if (c0 + 1 > rowA) s[nt][1] = -1e9f;
                if (c0 > rowB)     s[nt][2] = -1e9f;
                if (c0 + 1 > rowB) s[nt][3] = -1e9f;
            }
        }

        float mxA = -1e30f, mxB = -1e30f;
#pragma unroll
        for (int nt = 0; nt < 8; nt++) {
            mxA = fmaxf(mxA, fmaxf(s[nt][0], s[nt][1]));
            mxB = fmaxf(mxB, fmaxf(s[nt][2], s[nt][3]));
        }
        mxA = fmaxf(mxA, __shfl_xor_sync(0xffffffffu, mxA, 1));
        mxA = fmaxf(mxA, __shfl_xor_sync(0xffffffffu, mxA, 2));
        mxB = fmaxf(mxB, __shfl_xor_sync(0xffffffffu, mxB, 1));
        mxB = fmaxf(mxB, __shfl_xor_sync(0xffffffffu, mxB, 2));
        float mAn = fmaxf(mA, mxA), mBn = fmaxf(mB, mxB);
        float aAf = expf(mA - mAn), aBf = expf(mB - mBn);
        float pA = 0.f, pB = 0.f;
#pragma unroll
        for (int nt = 0; nt < 8; nt++) {
            s[nt][0] = expf(s[nt][0] - mAn);
            s[nt][1] = expf(s[nt][1] - mAn);
            s[nt][2] = expf(s[nt][2] - mBn);
            s[nt][3] = expf(s[nt][3] - mBn);
            pA += s[nt][0] + s[nt][1];
            pB += s[nt][2] + s[nt][3];
        }
        pA += __shfl_xor_sync(0xffffffffu, pA, 1);
        pA += __shfl_xor_sync(0xffffffffu, pA, 2);
        pB += __shfl_xor_sync(0xffffffffu, pB, 1);
        pB += __shfl_xor_sync(0xffffffffu, pB, 2);
        lA = lA * aAf + pA;
        lB = lB * aBf + pB;
        mA = mAn;
        mB = mBn;
#pragma unroll
        for (int t = 0; t < 16; t++) {
            o[t][0] *= aAf; o[t][1] *= aAf;
            o[t][2] *= aBf; o[t][3] *= aBf;
        }

#pragma unroll
        for (int ks = 0; ks < 4; ks++) {
            uint32_t ph[4], pl[4];
            ph[0] = splitpack(s[2 * ks][0],     s[2 * ks][1],     pl[0]);
            ph[1] = splitpack(s[2 * ks][2],     s[2 * ks][3],     pl[1]);
            ph[2] = splitpack(s[2 * ks + 1][0], s[2 * ks + 1][1], pl[2]);
            ph[3] = splitpack(s[2 * ks + 1][2], s[2 * ks + 1][3], pl[3]);
#pragma unroll
            for (int dt = 0; dt < 8; dt++) {
                uint32_t vo = vLd + (uint32_t)(ks * 16 * ATT_STRIDE * 2 + dt * 32);
                uint32_t vh[4], vl[4];
                ldsm_x4t(vh, Vh + vo);
                ldsm_x4t(vl, Vl + vo);
#pragma unroll
                for (int h = 0; h < 2; h++) {
                    float* od = o[dt * 2 + h];
                    mma_bf16(od, ph, vh + 2 * h);
                    mma_bf16(od, ph, vl + 2 * h);
                    mma_bf16(od, pl, vh + 2 * h);
                }
            }
        }
    }

    float liA = 1.0f / lA, liB = 1.0f / lB;
    int gRowA = qb * 64 + rowA;
    int gRowB = qb * 64 + rowB;
#pragma unroll
    for (int nt = 0; nt < 16; nt++) {
        int col = head * HDIM + nt * 8 + (lane & 3) * 2;
        uint32_t hA, lAo, hB, lBo;
        hA = splitpack(o[nt][0] * liA, o[nt][1] * liA, lAo);
        hB = splitpack(o[nt][2] * liB, o[nt][3] * liB, lBo);
        size_t iA = ((size_t)gRowA * HID + col) >> 1;
        size_t iB = ((size_t)gRowB * HID + col) >> 1;
        ((uint32_t*)ohi)[iA] = hA;
        ((uint32_t*)olo)[iA] = lAo;
        ((uint32_t*)ohi)[iB] = hB;
        ((uint32_t*)olo)[iB] = lBo;
    }
}

// ---------------- SiLU from fused [2048,16384] gate|up buffer ----------------
__global__ void silu_split_kernel(const float* __restrict__ fused,
                                  __nv_bfloat16* __restrict__ hi,
                                  __nv_bfloat16* __restrict__ lo) {
    int i = blockIdx.x * blockDim.x + threadIdx.x;
    int row = i >> 11;
    int c4  = i & 2047;
    size_t base = (size_t)row * (NFF2 / 4);
    float4 gv = ((const float4*)fused)[base + c4];
    float4 uv = ((const float4*)fused)[base + (FFD / 4) + c4];
    gv.x = gv.x / (1.f + expf(-gv.x)) * uv.x;
    gv.y = gv.y / (1.f + expf(-gv.y)) * uv.y;
    gv.z = gv.z / (1.f + expf(-gv.z)) * uv.z;
    gv.w = gv.w / (1.f + expf(-gv.w)) * uv.w;
    uint2 h, l;
    split4(gv, h, l);
    ((uint2*)hi)[i] = h;
    ((uint2*)lo)[i] = l;
}

// ---------------- host orchestration ----------------
static __nv_bfloat16 *s_ahi, *s_alo, *s_whi, *s_wlo, *s_qhi, *s_qlo;

static void run_split(const float* src, size_t n) {
    int nT = (int)(n / 16);
    split_kernel<<<nT / 256, 256>>>(src, s_whi, s_wlo, nT);
}
static void run_gemm(const float* b0, const float* b1, const float* b2,
                     const float* res, float* C, int M, int N, int K) {
    if (N >= 8192 || K >= 8192) {
        dim3 grid(N / 128, M / 256);
        gemm_big_kernel<<<grid, 512, BIG_SMEM>>>(
            s_ahi, s_alo, s_whi, s_wlo, b0, res, C, M, N, K);
    } else {
        dim3 grid(N / 128, M / 128);
        gemm_sml_kernel<<<grid, 256, SML_SMEM>>>(
            s_ahi, s_alo, s_whi, s_wlo, b0, b1, b2, res, C, M, N, K);
    }
}

extern "C" void kernel_launch(void* const* d_in, const int* in_sizes, int n_in,
                              void* d_out, int out_size) {
    const int*   ids    = (const int*)d_in[0];
    const float* emb    = (const float*)d_in[1];
    const float* Wq     = (const float*)d_in[2];
    const float* bq     = (const float*)d_in[3];
    const float* Wk     = (const float*)d_in[4];
    const float* bk     = (const float*)d_in[5];
    const float* Wv     = (const float*)d_in[6];
    const float* bv     = (const float*)d_in[7];
    const float* Wo     = (const float*)d_in[8];
    const float* ln1    = (const float*)d_in[9];
    const float* ln2    = (const float*)d_in[10];
    const float* Wg     = (const float*)d_in[11];
    const float* Wu     = (const float*)d_in[12];
    const float* Wd     = (const float*)d_in[13];
    const float* norm_w = (const float*)d_in[14];
    const float* Wlm    = (const float*)d_in[15];
    const float* blm    = (const float*)d_in[16];
    float* out = (float*)d_out;

    float* base = nullptr;
    float* rope_lut = nullptr;
    cudaGetSymbolAddress((void**)&base, g_scratch);
    cudaGetSymbolAddress((void**)&rope_lut, g_rope);
    cudaGetSymbolAddress((void**)&s_ahi, g_ahi);
    cudaGetSymbolAddress((void**)&s_alo, g_alo);
    cudaGetSymbolAddress((void**)&s_whi, g_whi);
    cudaGetSymbolAddress((void**)&s_wlo, g_wlo);
    cudaGetSymbolAddress((void**)&s_qhi, g_qkvhi);
    cudaGetSymbolAddress((void**)&s_qlo, g_qkvlo);

    float* hbuf  = base;
    float* qkv   = base + (size_t)SH;
    float* fbuf  = qkv + (size_t)SQ * NQKV;

    cudaFuncSetAttribute(attn_mma_kernel,
                         cudaFuncAttributeMaxDynamicSharedMemorySize, ATT_SMEM);
    cudaFuncSetAttribute(gemm_sml_kernel,
                         cudaFuncAttributeMaxDynamicSharedMemorySize, SML_SMEM);
    cudaFuncSetAttribute(gemm_big_kernel,
                         cudaFuncAttributeMaxDynamicSharedMemorySize, BIG_SMEM);

    rope_lut_kernel<<<SQ, 64>>>(rope_lut);

    for (int l = 0; l < NLAYER; l++) {
        const float* Wql = Wq + (size_t)l * HID * HID;
        const float* bql = bq + (size_t)l * HID;
        const float* Wkl = Wk + (size_t)l * HID * (NKVH * HDIM);
        const float* bkl = bk + (size_t)l * (NKVH * HDIM);
        const float* Wvl = Wv + (size_t)l * HID * (NKVH * HDIM);
        const float* bvl = bv + (size_t)l * (NKVH * HDIM);
        const float* Wol = Wo + (size_t)l * HID * HID;
        const float* l1  = ln1 + (size_t)l * HID;
        const float* l2  = ln2 + (size_t)l * HID;
        const float* Wgl = Wg + (size_t)l * HID * FFD;
        const float* Wul = Wu + (size_t)l * HID * FFD;
        const float* Wdl = Wd + (size_t)l * FFD * HID;

        // ---- fused QKV projection ----
        {
            int nT = (int)((size_t)HID * HID / 16);
            split2d_kernel<<<nT / 256, 256>>>(
                Wql, s_whi, s_wlo, HID / 8, NQKV / 8, nT);
        }
        {
            int nT = HID * 1024 / 16;
            splitkv_kernel<<<nT / 256, 256>>>(Wkl, Wvl, s_whi, s_wlo, nT);
        }
        if (l == 0)
            rmsnorm_split_kernel<<<SQ, 256>>>(nullptr, ids, emb, l1, hbuf,
                                              s_ahi, s_alo);
        else
            rmsnorm_split_kernel<<<SQ, 256>>>(hbuf, nullptr, nullptr, l1,
                                              nullptr, s_ahi, s_alo);
        run_gemm(bql, bkl, bvl, nullptr, qkv, SQ, NQKV, HID);

        // ---- RoPE + split (LUT) ----
        dim3 rgrid(SQ, NHEAD + 2 * NKVH);
        rope_split_kernel<<<rgrid, 64>>>(qkv, rope_lut, s_qhi, s_qlo);

        // ---- attention -> activation planes ----
        dim3 agrid(NHEAD, SQ / 64);
        attn_mma_kernel<<<agrid, 128, ATT_SMEM>>>(s_qhi, s_qlo, s_ahi, s_alo);

        // ---- O projection (+residual) ----
        run_split(Wol, (size_t)HID * HID);
        run_gemm(nullptr, nullptr, nullptr, hbuf, hbuf, SQ, HID, HID);

        // ---- fused gate|up MLP (contiguous halves) ----
        rmsnorm_split_kernel<<<SQ, 256>>>(hbuf, nullptr, nullptr, l2,
                                          nullptr, s_ahi, s_alo);
        {
            int nT = (int)((size_t)HID * FFD / 16);
            split2d_kernel<<<nT / 256, 256>>>(
                Wgl, s_whi, s_wlo, FFD / 8, NFF2 / 8, nT);
            split2d_kernel<<<nT / 256, 256>>>(
                Wul, s_whi + FFD, s_wlo + FFD, FFD / 8, NFF2 / 8, nT);
        }
        run_gemm(nullptr, nullptr, nullptr, nullptr, fbuf, SQ, NFF2, HID);
        silu_split_kernel<<<SFF / 4 / 256, 256>>>(fbuf, s_ahi, s_alo);
        run_split(Wdl, (size_t)FFD * HID);
        run_gemm(nullptr, nullptr, nullptr, hbuf, hbuf, SQ, HID, FFD);
    }

    rmsnorm_split_kernel<<<SQ, 256>>>(hbuf, nullptr, nullptr, norm_w,
                                      nullptr, s_ahi, s_alo);
    run_split(Wlm, (size_t)HID * VOC);
    run_gemm(blm, nullptr, nullptr, nullptr, out, SQ, VOC, HID);
}